// round 14
// baseline (speedup 1.0000x reference)
#include <cuda_runtime.h>
#include <cuda_fp16.h>
#include <cstdint>
#include <cmath>

// ===========================================================================
// SwinTransformerBlock on GB300 (family-portable PTX, mma.sync fp16).
// R14: keep R13's 2-head-per-block attention (full-128B gathers); REVERT the
// proj+LN2 fusion to R11's separate proj hgemm (2 CTAs/SM) + LN2 kernel —
// the 1-CTA/SM fused kernel was the regression suspect in R13.
// ===========================================================================

#define MT 131072

__device__ __align__(16) __half g_xni [(size_t)MT*256];
__device__ __align__(16) __half g_qkv [(size_t)MT*768];
__device__ __align__(16) __half g_aoi [(size_t)MT*256];
__device__ float                g_x2  [(size_t)MT*256];
__device__ __align__(16) __half g_hidi[(size_t)MT*1024];
__device__ __align__(16) __half g_qkvwi[768*256];
__device__ __align__(16) __half g_projwi[256*256];
__device__ __align__(16) __half g_fc1wi[1024*256];
__device__ __align__(16) __half g_fc2wi[256*1024];
__device__ __align__(16) __half g_cb  [256*8*4096];

// ---------------------------------------------------------------------------
__device__ __forceinline__ uint32_t smem_u32(const void* p) {
    uint32_t a;
    asm("{ .reg .u64 t; cvta.to.shared.u64 t, %1; cvt.u32.u64 %0, t; }" : "=r"(a) : "l"(p));
    return a;
}
#define CP_ASYNC16(sa, ga) \
    asm volatile("cp.async.cg.shared.global [%0], [%1], 16;" :: "r"(sa), "l"(ga))
#define CP_COMMIT() asm volatile("cp.async.commit_group;" ::: "memory")
#define CP_WAIT1()  asm volatile("cp.async.wait_group 1;" ::: "memory")
#define CP_WAIT0()  asm volatile("cp.async.wait_group 0;" ::: "memory")

#define LDSM_X4(r0,r1,r2,r3, a) \
    asm volatile("ldmatrix.sync.aligned.m8n8.x4.shared.b16 {%0,%1,%2,%3}, [%4];" \
        : "=r"(r0), "=r"(r1), "=r"(r2), "=r"(r3) : "r"(a))

#define MMA16816(c, a, b0, b1) \
    asm volatile("mma.sync.aligned.m16n8k16.row.col.f32.f16.f16.f32 " \
        "{%0,%1,%2,%3}, {%4,%5,%6,%7}, {%8,%9}, {%0,%1,%2,%3};" \
        : "+f"((c)[0]), "+f"((c)[1]), "+f"((c)[2]), "+f"((c)[3]) \
        : "r"((a)[0]), "r"((a)[1]), "r"((a)[2]), "r"((a)[3]), "r"(b0), "r"(b1))

__device__ __forceinline__ uint32_t pack_h2(float a, float b) {
    __half2 t = __floats2half2_rn(a, b);
    return *(uint32_t*)&t;
}
__device__ __forceinline__ uint2 pack_h4(float4 v) {
    uint2 u;
    u.x = pack_h2(v.x, v.y);
    u.y = pack_h2(v.z, v.w);
    return u;
}
__device__ __forceinline__ float gelu_f(float v) {
    return 0.5f * v * (1.0f + erff(v * 0.7071067811865476f));
}

// ---------------------------------------------------------------------------
// Combined weight conversion: fp32 [N,K] -> fp16 [N,K]
// ---------------------------------------------------------------------------
__global__ void wconv_all(const float* w0, __half* o0,
                          const float* w1, __half* o1,
                          const float* w2, __half* o2,
                          const float* w3, __half* o3) {
    int i = blockIdx.x * 256 + threadIdx.x;
    const float* w; __half* o; int li;
    if (i < 49152)        { w = w0; o = o0; li = i; }
    else if (i < 65536)   { w = w1; o = o1; li = i - 49152; }
    else if (i < 131072)  { w = w2; o = o2; li = i - 65536; }
    else if (i < 196608)  { w = w3; o = o3; li = i - 131072; }
    else return;
    float4 v = *(const float4*)(w + (size_t)li * 4);
    *(uint2*)(o + (size_t)li * 4) = pack_h4(v);
}

// ---------------------------------------------------------------------------
// Combined bias+mask table (fp16)
// ---------------------------------------------------------------------------
__global__ void cb_prep(const float* __restrict__ bt, const float* __restrict__ mask,
                        __half* __restrict__ cb) {
    int lin = blockIdx.x * 256 + threadIdx.x;
    int m    = (lin & 31) * 2;
    int n    = (lin >> 5) & 63;
    int head = (lin >> 11) & 7;
    int wimg = lin >> 14;
    float mk0 = mask[wimg*4096 + n*64 + m];
    float mk1 = mask[wimg*4096 + n*64 + m + 1];
    int ri0 = ((n>>3) - (m>>3) + 7)*15 + ((n&7) - (m&7) + 7);
    int ri1 = ((n>>3) - ((m+1)>>3) + 7)*15 + ((n&7) - ((m+1)&7) + 7);
    float b0 = bt[ri0*8 + head] + mk0;
    float b1 = bt[ri1*8 + head] + mk1;
    *(uint32_t*)(cb + (size_t)lin * 2) = pack_h2(b0, b1);
}

// ---------------------------------------------------------------------------
// LayerNorm (C=256): one warp/row, fp16 out
// ---------------------------------------------------------------------------
__global__ __launch_bounds__(256) void ln_kernel(
    const float* __restrict__ x, const float* __restrict__ g,
    const float* __restrict__ b, __half* __restrict__ out)
{
    size_t row = (size_t)blockIdx.x * 8 + (threadIdx.x >> 5);
    int lane = threadIdx.x & 31;
    const float* xr = x + row * 256 + lane * 8;
    float4 v0 = *(const float4*)(xr);
    float4 v1 = *(const float4*)(xr + 4);

    float s  = v0.x+v0.y+v0.z+v0.w + v1.x+v1.y+v1.z+v1.w;
    float sq = v0.x*v0.x+v0.y*v0.y+v0.z*v0.z+v0.w*v0.w
             + v1.x*v1.x+v1.y*v1.y+v1.z*v1.z+v1.w*v1.w;
    #pragma unroll
    for (int o = 16; o > 0; o >>= 1) {
        s  += __shfl_xor_sync(0xffffffffu, s,  o);
        sq += __shfl_xor_sync(0xffffffffu, sq, o);
    }
    float mean = s * (1.0f/256.0f);
    float rstd = rsqrtf(sq * (1.0f/256.0f) - mean*mean + 1e-5f);

    const float4 g0 = *(const float4*)(g + lane*8);
    const float4 g1 = *(const float4*)(g + lane*8 + 4);
    const float4 b0 = *(const float4*)(b + lane*8);
    const float4 b1 = *(const float4*)(b + lane*8 + 4);

    float4 o0, o1;
    o0.x=(v0.x-mean)*rstd*g0.x+b0.x; o0.y=(v0.y-mean)*rstd*g0.y+b0.y;
    o0.z=(v0.z-mean)*rstd*g0.z+b0.z; o0.w=(v0.w-mean)*rstd*g0.w+b0.w;
    o1.x=(v1.x-mean)*rstd*g1.x+b1.x; o1.y=(v1.y-mean)*rstd*g1.y+b1.y;
    o1.z=(v1.z-mean)*rstd*g1.z+b1.z; o1.w=(v1.w-mean)*rstd*g1.w+b1.w;

    uint4 u;
    u.x = pack_h2(o0.x, o0.y); u.y = pack_h2(o0.z, o0.w);
    u.z = pack_h2(o1.x, o1.y); u.w = pack_h2(o1.z, o1.w);
    *(uint4*)(out + row * 256 + lane * 8) = u;
}

// ---------------------------------------------------------------------------
// fp16 tensor-core GEMM (plateaued config): CTA 128x128, warp 32x64,
// 3-stage cp.async, 2 CTAs/SM, one sync per chunk.
// MODE: 1=bias+res fp32; 2=bias+gelu fp16; 3=bias fp16.
// ---------------------------------------------------------------------------
#define HSTAGE 32768
#define HSMEM  (3*HSTAGE)

template<int MODE>
__global__ __launch_bounds__(256, 2) void hgemm(
    const __half* __restrict__ A, const __half* __restrict__ B,
    const float* __restrict__ bias, const float* __restrict__ res,
    void* __restrict__ Cout, int N, int K)
{
    extern __shared__ char sm[];
    const uint32_t sbase = smem_u32(sm);
    const int tid  = threadIdx.x;
    const int lane = tid & 31;
    const int warp = tid >> 5;
    const int wr   = warp >> 1;
    const int wc   = warp & 1;
    const size_t gr0 = (size_t)blockIdx.y * 128;
    const int    gc0 = blockIdx.x * 128;
    const int CCH = K >> 6;

    const int lrow = tid >> 3;
    const int lkc  = tid & 7;

    auto load_stage = [&](int c) {
        uint32_t sA = sbase + (c % 3) * HSTAGE;
        uint32_t sB = sA + 16384;
        const __half* Ab = A + c*64 + lkc*8;
        const __half* Bb = B + c*64 + lkc*8;
        #pragma unroll
        for (int p = 0; p < 4; p++) {
            int row = lrow + p*32;
            uint32_t off = row*128 + (((uint32_t)(lkc ^ (row & 7))) << 4);
            CP_ASYNC16(sA + off, Ab + (gr0 + row) * (size_t)K);
            CP_ASYNC16(sB + off, Bb + (size_t)(gc0 + row) * K);
        }
    };

    load_stage(0); CP_COMMIT();
    load_stage(1); CP_COMMIT();

    float acc[2][8][4];
    #pragma unroll
    for (int mt = 0; mt < 2; mt++)
        #pragma unroll
        for (int nt = 0; nt < 8; nt++)
            #pragma unroll
            for (int q = 0; q < 4; q++) acc[mt][nt][q] = 0.0f;

    const int lr8  = (lane & 7) + ((lane >> 3) & 1) * 8;
    const int lkhi = lane >> 4;

    for (int c = 0; c < CCH; c++) {
        CP_WAIT1();
        __syncthreads();
        if (c + 2 < CCH) load_stage(c + 2);
        CP_COMMIT();

        uint32_t sA = sbase + (c % 3) * HSTAGE;
        uint32_t sB = sA + 16384;

        #pragma unroll
        for (int ks = 0; ks < 4; ks++) {
            int kc = 2*ks + lkhi;
            uint32_t a[2][4];
            #pragma unroll
            for (int mt = 0; mt < 2; mt++) {
                int row = wr*32 + mt*16 + lr8;
                LDSM_X4(a[mt][0], a[mt][1], a[mt][2], a[mt][3],
                        sA + row*128 + ((uint32_t)(kc ^ (row & 7)) << 4));
            }
            uint32_t b[4][4];
            #pragma unroll
            for (int nq = 0; nq < 4; nq++) {
                int row = wc*64 + nq*16 + lr8;
                LDSM_X4(b[nq][0], b[nq][1], b[nq][2], b[nq][3],
                        sB + row*128 + ((uint32_t)(kc ^ (row & 7)) << 4));
            }
            #pragma unroll
            for (int mt = 0; mt < 2; mt++)
                #pragma unroll
                for (int nt = 0; nt < 8; nt++)
                    MMA16816(acc[mt][nt], a[mt], b[nt>>1][nt&1], b[nt>>1][2+(nt&1)]);
        }
    }

    CP_WAIT0();
    __syncthreads();
    float* epi = (float*)sm;
    const int mrow = lane >> 2;
    const int ncol = (lane & 3) * 2;
    #pragma unroll
    for (int mt = 0; mt < 2; mt++)
        #pragma unroll
        for (int half = 0; half < 2; half++) {
            int r = wr*32 + mt*16 + half*8 + mrow;
            #pragma unroll
            for (int nt = 0; nt < 8; nt++) {
                int cc = wc*64 + nt*8 + ncol;
                *(float2*)&epi[r*132 + cc] =
                    make_float2(acc[mt][nt][half*2], acc[mt][nt][half*2+1]);
            }
        }
    __syncthreads();

    #pragma unroll 4
    for (int it = 0; it < 16; it++) {
        int idx = it*256 + tid;
        int row = idx >> 5;
        int c4  = (idx & 31) * 4;
        int gcol = gc0 + c4;
        float4 v = *(float4*)&epi[row*132 + c4];
        float4 bb = *(const float4*)(bias + gcol);
        v.x += bb.x; v.y += bb.y; v.z += bb.z; v.w += bb.w;
        size_t grow = gr0 + row;
        if (MODE == 1) {
            float4 r = *(const float4*)(res + grow * (size_t)N + gcol);
            v.x += r.x; v.y += r.y; v.z += r.z; v.w += r.w;
        }
        if (MODE == 2) {
            v.x = gelu_f(v.x); v.y = gelu_f(v.y); v.z = gelu_f(v.z); v.w = gelu_f(v.w);
        }
        if (MODE == 2 || MODE == 3) {
            *(uint2*)((__half*)Cout + grow * (size_t)N + gcol) = pack_h4(v);
        } else {
            *(float4*)((float*)Cout + grow * (size_t)N + gcol) = v;
        }
    }
}

// ---------------------------------------------------------------------------
// Fused shifted-window attention, 2 heads per block (256 threads, 8 warps).
// Warps 0-3 -> head 2hp, warps 4-7 -> head 2hp+1, own smem planes.
// ---------------------------------------------------------------------------
__global__ __launch_bounds__(256) void attn_kernel(
    const __half* __restrict__ qkv, const __half* __restrict__ cb,
    __half* __restrict__ aoi)
{
    __shared__ __align__(16) __half qk_s[2*64*64];   // 16 KB
    __shared__ __align__(16) __half v_s[2*32*64];    //  8 KB
    __shared__ __align__(16) __half cb_s[2*64*64];   // 16 KB

    const int hp   = blockIdx.x;
    const int w    = blockIdx.y;
    const int bimg = w >> 8;
    const int wimg = w & 255;
    const int wh   = wimg >> 4;
    const int ww   = wimg & 15;
    const int tid  = threadIdx.x;
    const int lane = tid & 31;
    const int wp   = tid >> 5;
    const float scale = 0.17677669529663689f;

    // ---- stage combined bias+mask for both heads (16 KB = 1024 uint4) ----
    {
        const uint4* src = (const uint4*)(cb + ((size_t)wimg*8 + 2*hp)*4096);
        uint4* dst = (uint4*)cb_s;
        #pragma unroll
        for (int i = 0; i < 4; i++) dst[tid + 256*i] = src[tid + 256*i];
    }

    // ---- gather q,k,v: 64 channels (both heads) per token, coalesced ----
    {
        const int col = (tid & 31) * 2;
        const int hsel = col >> 5;
        const int d = col & 31;
        const uint32_t ch = d >> 3;
        const uint32_t wi = (d & 7) * 2;
        char* qkp = (char*)qk_s + hsel*8192;
        char* vp  = (char*)v_s  + hsel*4096;
        #pragma unroll
        for (int it = 0; it < 8; it++) {
            int r = (tid >> 5) + 8*it;
            int i = r >> 3, j = r & 7;
            int oh = (wh*8 + i + 4) & 127;
            int ow = (ww*8 + j + 4) & 127;
            size_t tok = (size_t)bimg*16384 + oh*128 + ow;
            const __half* src = qkv + tok*768 + hp*64 + col;
            __half2 qh = *(const __half2*)(src);
            __half2 kh = *(const __half2*)(src + 256);
            __half2 vh = *(const __half2*)(src + 512);
            float2 qf = __half22float2(qh);
            uint32_t qp = pack_h2(qf.x * scale, qf.y * scale);
            uint32_t qa = r*128 + ((ch ^ (uint32_t)(r&7))<<4) + wi;
            uint32_t ka = r*128 + (((ch+4) ^ (uint32_t)(r&7))<<4) + wi;
            *(uint32_t*)(qkp + qa) = qp;
            *(uint32_t*)(qkp + ka) = *(uint32_t*)&kh;
            uint32_t va0 = d*128     + ((uint32_t)((r>>3) ^ (d&7))    <<4) + (r&7)*2;
            uint32_t va1 = (d+1)*128 + ((uint32_t)((r>>3) ^ ((d+1)&7))<<4) + (r&7)*2;
            *(__half*)(vp + va0) = __low2half(vh);
            *(__half*)(vp + va1) = __high2half(vh);
        }
    }
    __syncthreads();

    const int g   = wp >> 2;
    const int wpl = wp & 3;
    const uint32_t qkb = smem_u32(qk_s) + g*8192;
    const uint32_t vb  = smem_u32(v_s)  + g*4096;
    const __half* cbp  = cb_s + g*4096;

    const int lr8  = (lane & 7) + ((lane >> 3) & 1) * 8;
    const int lkhi = lane >> 4;

    float acc[8][4];
    #pragma unroll
    for (int nt = 0; nt < 8; nt++)
        #pragma unroll
        for (int q = 0; q < 4; q++) acc[nt][q] = 0.0f;

    #pragma unroll
    for (int ks = 0; ks < 2; ks++) {
        int arow = wpl*16 + lr8;
        int kcq  = 2*ks + lkhi;
        uint32_t a[4];
        LDSM_X4(a[0], a[1], a[2], a[3],
                qkb + arow*128 + ((uint32_t)(kcq ^ (arow & 7)) << 4));
        uint32_t b[4][4];
        #pragma unroll
        for (int nq = 0; nq < 4; nq++) {
            int brow = nq*16 + lr8;
            int kck  = 4 + 2*ks + lkhi;
            LDSM_X4(b[nq][0], b[nq][1], b[nq][2], b[nq][3],
                    qkb + brow*128 + ((uint32_t)(kck ^ (brow & 7)) << 4));
        }
        #pragma unroll
        for (int nt = 0; nt < 8; nt++)
            MMA16816(acc[nt], a, b[nt>>1][nt&1], b[nt>>1][2+(nt&1)]);
    }

    const int r0 = wpl*16 + (lane >> 2);
    const int r1 = r0 + 8;
    const int mcol = (lane & 3) * 2;
    float mx0 = -1e30f, mx1 = -1e30f;
    #pragma unroll
    for (int nt = 0; nt < 8; nt++) {
        __half2 c0 = *(__half2*)&cbp[r0*64 + nt*8 + mcol];
        __half2 c1 = *(__half2*)&cbp[r1*64 + nt*8 + mcol];
        float2 f0 = __half22float2(c0);
        float2 f1 = __half22float2(c1);
        acc[nt][0] += f0.x; acc[nt][1] += f0.y;
        acc[nt][2] += f1.x; acc[nt][3] += f1.y;
        mx0 = fmaxf(mx0, fmaxf(acc[nt][0], acc[nt][1]));
        mx1 = fmaxf(mx1, fmaxf(acc[nt][2], acc[nt][3]));
    }
    mx0 = fmaxf(mx0, __shfl_xor_sync(0xffffffffu, mx0, 1));
    mx0 = fmaxf(mx0, __shfl_xor_sync(0xffffffffu, mx0, 2));
    mx1 = fmaxf(mx1, __shfl_xor_sync(0xffffffffu, mx1, 1));
    mx1 = fmaxf(mx1, __shfl_xor_sync(0xffffffffu, mx1, 2));
    float s0 = 0.0f, s1 = 0.0f;
    #pragma unroll
    for (int nt = 0; nt < 8; nt++) {
        acc[nt][0] = __expf(acc[nt][0] - mx0); s0 += acc[nt][0];
        acc[nt][1] = __expf(acc[nt][1] - mx0); s0 += acc[nt][1];
        acc[nt][2] = __expf(acc[nt][2] - mx1); s1 += acc[nt][2];
        acc[nt][3] = __expf(acc[nt][3] - mx1); s1 += acc[nt][3];
    }
    s0 += __shfl_xor_sync(0xffffffffu, s0, 1);
    s0 += __shfl_xor_sync(0xffffffffu, s0, 2);
    s1 += __shfl_xor_sync(0xffffffffu, s1, 1);
    s1 += __shfl_xor_sync(0xffffffffu, s1, 2);
    float inv0 = 1.0f / s0, inv1 = 1.0f / s1;

    float o[4][4];
    #pragma unroll
    for (int nt = 0; nt < 4; nt++)
        #pragma unroll
        for (int q = 0; q < 4; q++) o[nt][q] = 0.0f;

    #pragma unroll
    for (int kt = 0; kt < 4; kt++) {
        uint32_t a[4];
        a[0] = pack_h2(acc[2*kt][0]*inv0,   acc[2*kt][1]*inv0);
        a[1] = pack_h2(acc[2*kt][2]*inv1,   acc[2*kt][3]*inv1);
        a[2] = pack_h2(acc[2*kt+1][0]*inv0, acc[2*kt+1][1]*inv0);
        a[3] = pack_h2(acc[2*kt+1][2]*inv1, acc[2*kt+1][3]*inv1);
        uint32_t b[2][4];
        #pragma unroll
        for (int nq = 0; nq < 2; nq++) {
            int brow = nq*16 + lr8;
            int kc   = 2*kt + lkhi;
            LDSM_X4(b[nq][0], b[nq][1], b[nq][2], b[nq][3],
                    vb + brow*128 + ((uint32_t)(kc ^ (brow & 7)) << 4));
        }
        #pragma unroll
        for (int nt = 0; nt < 4; nt++)
            MMA16816(o[nt], a, b[nt>>1][nt&1], b[nt>>1][2+(nt&1)]);
    }

    const int head = 2*hp + g;
    #pragma unroll
    for (int s = 0; s < 2; s++) {
        int n = s ? r1 : r0;
        int i = n >> 3, j = n & 7;
        int oh = (wh*8 + i + 4) & 127;
        int ow = (ww*8 + j + 4) & 127;
        size_t tok = (size_t)bimg*16384 + oh*128 + ow;
        __half* base = aoi + tok*256 + head*32;
        #pragma unroll
        for (int nt = 0; nt < 4; nt++) {
            int c = nt*8 + (lane & 3)*2;
            *(uint32_t*)(base + c) = pack_h2(o[nt][s*2], o[nt][s*2+1]);
        }
    }
}

// ---------------------------------------------------------------------------
extern "C" void kernel_launch(void* const* d_in, const int* in_sizes, int n_in,
                              void* d_out, int out_size)
{
    const float* x     = (const float*)d_in[0];
    const float* mask  = (const float*)d_in[1];
    const float* n1g   = (const float*)d_in[2];
    const float* n1b   = (const float*)d_in[3];
    const float* qkvw  = (const float*)d_in[4];
    const float* qkvb  = (const float*)d_in[5];
    const float* relb  = (const float*)d_in[6];
    const float* projw = (const float*)d_in[7];
    const float* projb = (const float*)d_in[8];
    const float* n2g   = (const float*)d_in[9];
    const float* n2b   = (const float*)d_in[10];
    const float* fc1w  = (const float*)d_in[11];
    const float* fc1b  = (const float*)d_in[12];
    const float* fc2w  = (const float*)d_in[13];
    const float* fc2b  = (const float*)d_in[14];
    float* out = (float*)d_out;

    __half *xni, *qkv, *aoi, *hidi, *qkvwi, *projwi, *fc1wi, *fc2wi, *cb;
    float *x2;
    cudaGetSymbolAddress((void**)&xni,   g_xni);
    cudaGetSymbolAddress((void**)&qkv,   g_qkv);
    cudaGetSymbolAddress((void**)&aoi,   g_aoi);
    cudaGetSymbolAddress((void**)&x2,    g_x2);
    cudaGetSymbolAddress((void**)&hidi,  g_hidi);
    cudaGetSymbolAddress((void**)&qkvwi, g_qkvwi);
    cudaGetSymbolAddress((void**)&projwi,g_projwi);
    cudaGetSymbolAddress((void**)&fc1wi, g_fc1wi);
    cudaGetSymbolAddress((void**)&fc2wi, g_fc2wi);
    cudaGetSymbolAddress((void**)&cb,    g_cb);

    cudaFuncSetAttribute(hgemm<1>, cudaFuncAttributeMaxDynamicSharedMemorySize, HSMEM);
    cudaFuncSetAttribute(hgemm<2>, cudaFuncAttributeMaxDynamicSharedMemorySize, HSMEM);
    cudaFuncSetAttribute(hgemm<3>, cudaFuncAttributeMaxDynamicSharedMemorySize, HSMEM);

    wconv_all<<<768, 256>>>(qkvw, qkvwi, projw, projwi, fc1w, fc1wi, fc2w, fc2wi);
    cb_prep<<<16384, 256>>>(relb, mask, cb);

    // 1. LN1 -> fp16
    ln_kernel<<<MT/8, 256>>>(x, n1g, n1b, xni);
    // 2. QKV: [131072,256] @ [768,256]^T -> fp16
    hgemm<3><<<dim3(6, MT/128), 256, HSMEM>>>(xni, qkvwi, qkvb, nullptr, qkv, 768, 256);
    // 3. windowed attention (tensor-core, 2 heads/block)
    attn_kernel<<<dim3(4, 2048), 256>>>(qkv, cb, aoi);
    // 4. proj + residual(x) -> x2 fp32
    hgemm<1><<<dim3(2, MT/128), 256, HSMEM>>>(aoi, projwi, projb, x, x2, 256, 256);
    // 5. LN2 -> fp16
    ln_kernel<<<MT/8, 256>>>(x2, n2g, n2b, xni);
    // 6. FC1 + gelu -> fp16 hidden
    hgemm<2><<<dim3(8, MT/128), 256, HSMEM>>>(xni, fc1wi, fc1b, nullptr, hidi, 1024, 256);
    // 7. FC2 + residual(x2) -> out fp32
    hgemm<1><<<dim3(2, MT/128), 256, HSMEM>>>(hidi, fc2wi, fc2b, x2, out, 256, 1024);
}

// round 15
// speedup vs baseline: 1.0129x; 1.0129x over previous
#include <cuda_runtime.h>
#include <cuda_fp16.h>
#include <cstdint>
#include <cmath>

// ===========================================================================
// SwinTransformerBlock on GB300 (family-portable PTX, mma.sync fp16).
// R15 = R11 exactly (best config: 128x128 GEMM 2 CTAs/SM one-sync loop,
// 1-head attention w/ cb table + register P), plus ONE change:
// fp16 smem staging in the GEMM epilogue for fp16-output modes (QKV, FC1)
// — halves epilogue smem traffic and global-store loop length.
// ===========================================================================

#define MT 131072

__device__ __align__(16) __half g_xni [(size_t)MT*256];
__device__ __align__(16) __half g_qkv [(size_t)MT*768];
__device__ __align__(16) __half g_aoi [(size_t)MT*256];
__device__ float                g_x2  [(size_t)MT*256];
__device__ __align__(16) __half g_hidi[(size_t)MT*1024];
__device__ __align__(16) __half g_qkvwi[768*256];
__device__ __align__(16) __half g_projwi[256*256];
__device__ __align__(16) __half g_fc1wi[1024*256];
__device__ __align__(16) __half g_fc2wi[256*1024];
__device__ __align__(16) __half g_cb  [256*8*4096];

// ---------------------------------------------------------------------------
__device__ __forceinline__ uint32_t smem_u32(const void* p) {
    uint32_t a;
    asm("{ .reg .u64 t; cvta.to.shared.u64 t, %1; cvt.u32.u64 %0, t; }" : "=r"(a) : "l"(p));
    return a;
}
#define CP_ASYNC16(sa, ga) \
    asm volatile("cp.async.cg.shared.global [%0], [%1], 16;" :: "r"(sa), "l"(ga))
#define CP_COMMIT() asm volatile("cp.async.commit_group;" ::: "memory")
#define CP_WAIT1()  asm volatile("cp.async.wait_group 1;" ::: "memory")
#define CP_WAIT0()  asm volatile("cp.async.wait_group 0;" ::: "memory")

#define LDSM_X4(r0,r1,r2,r3, a) \
    asm volatile("ldmatrix.sync.aligned.m8n8.x4.shared.b16 {%0,%1,%2,%3}, [%4];" \
        : "=r"(r0), "=r"(r1), "=r"(r2), "=r"(r3) : "r"(a))

#define MMA16816(c, a, b0, b1) \
    asm volatile("mma.sync.aligned.m16n8k16.row.col.f32.f16.f16.f32 " \
        "{%0,%1,%2,%3}, {%4,%5,%6,%7}, {%8,%9}, {%0,%1,%2,%3};" \
        : "+f"((c)[0]), "+f"((c)[1]), "+f"((c)[2]), "+f"((c)[3]) \
        : "r"((a)[0]), "r"((a)[1]), "r"((a)[2]), "r"((a)[3]), "r"(b0), "r"(b1))

__device__ __forceinline__ uint32_t pack_h2(float a, float b) {
    __half2 t = __floats2half2_rn(a, b);
    return *(uint32_t*)&t;
}
__device__ __forceinline__ uint2 pack_h4(float4 v) {
    uint2 u;
    u.x = pack_h2(v.x, v.y);
    u.y = pack_h2(v.z, v.w);
    return u;
}
__device__ __forceinline__ float gelu_f(float v) {
    return 0.5f * v * (1.0f + erff(v * 0.7071067811865476f));
}

// ---------------------------------------------------------------------------
// Combined weight conversion: fp32 [N,K] -> fp16 [N,K]
// ---------------------------------------------------------------------------
__global__ void wconv_all(const float* w0, __half* o0,
                          const float* w1, __half* o1,
                          const float* w2, __half* o2,
                          const float* w3, __half* o3) {
    int i = blockIdx.x * 256 + threadIdx.x;
    const float* w; __half* o; int li;
    if (i < 49152)        { w = w0; o = o0; li = i; }
    else if (i < 65536)   { w = w1; o = o1; li = i - 49152; }
    else if (i < 131072)  { w = w2; o = o2; li = i - 65536; }
    else if (i < 196608)  { w = w3; o = o3; li = i - 131072; }
    else return;
    float4 v = *(const float4*)(w + (size_t)li * 4);
    *(uint2*)(o + (size_t)li * 4) = pack_h4(v);
}

// ---------------------------------------------------------------------------
// Combined bias+mask table (fp16)
// ---------------------------------------------------------------------------
__global__ void cb_prep(const float* __restrict__ bt, const float* __restrict__ mask,
                        __half* __restrict__ cb) {
    int lin = blockIdx.x * 256 + threadIdx.x;
    int m    = (lin & 31) * 2;
    int n    = (lin >> 5) & 63;
    int head = (lin >> 11) & 7;
    int wimg = lin >> 14;
    float mk0 = mask[wimg*4096 + n*64 + m];
    float mk1 = mask[wimg*4096 + n*64 + m + 1];
    int ri0 = ((n>>3) - (m>>3) + 7)*15 + ((n&7) - (m&7) + 7);
    int ri1 = ((n>>3) - ((m+1)>>3) + 7)*15 + ((n&7) - ((m+1)&7) + 7);
    float b0 = bt[ri0*8 + head] + mk0;
    float b1 = bt[ri1*8 + head] + mk1;
    *(uint32_t*)(cb + (size_t)lin * 2) = pack_h2(b0, b1);
}

// ---------------------------------------------------------------------------
// LayerNorm (C=256): one warp/row, fp16 out
// ---------------------------------------------------------------------------
__global__ __launch_bounds__(256) void ln_kernel(
    const float* __restrict__ x, const float* __restrict__ g,
    const float* __restrict__ b, __half* __restrict__ out)
{
    size_t row = (size_t)blockIdx.x * 8 + (threadIdx.x >> 5);
    int lane = threadIdx.x & 31;
    const float* xr = x + row * 256 + lane * 8;
    float4 v0 = *(const float4*)(xr);
    float4 v1 = *(const float4*)(xr + 4);

    float s  = v0.x+v0.y+v0.z+v0.w + v1.x+v1.y+v1.z+v1.w;
    float sq = v0.x*v0.x+v0.y*v0.y+v0.z*v0.z+v0.w*v0.w
             + v1.x*v1.x+v1.y*v1.y+v1.z*v1.z+v1.w*v1.w;
    #pragma unroll
    for (int o = 16; o > 0; o >>= 1) {
        s  += __shfl_xor_sync(0xffffffffu, s,  o);
        sq += __shfl_xor_sync(0xffffffffu, sq, o);
    }
    float mean = s * (1.0f/256.0f);
    float rstd = rsqrtf(sq * (1.0f/256.0f) - mean*mean + 1e-5f);

    const float4 g0 = *(const float4*)(g + lane*8);
    const float4 g1 = *(const float4*)(g + lane*8 + 4);
    const float4 b0 = *(const float4*)(b + lane*8);
    const float4 b1 = *(const float4*)(b + lane*8 + 4);

    float4 o0, o1;
    o0.x=(v0.x-mean)*rstd*g0.x+b0.x; o0.y=(v0.y-mean)*rstd*g0.y+b0.y;
    o0.z=(v0.z-mean)*rstd*g0.z+b0.z; o0.w=(v0.w-mean)*rstd*g0.w+b0.w;
    o1.x=(v1.x-mean)*rstd*g1.x+b1.x; o1.y=(v1.y-mean)*rstd*g1.y+b1.y;
    o1.z=(v1.z-mean)*rstd*g1.z+b1.z; o1.w=(v1.w-mean)*rstd*g1.w+b1.w;

    uint4 u;
    u.x = pack_h2(o0.x, o0.y); u.y = pack_h2(o0.z, o0.w);
    u.z = pack_h2(o1.x, o1.y); u.w = pack_h2(o1.z, o1.w);
    *(uint4*)(out + row * 256 + lane * 8) = u;
}

// ---------------------------------------------------------------------------
// fp16 tensor-core GEMM: CTA 128x128, warp 32x64, 3-stage cp.async,
// 2 CTAs/SM, one sync per chunk. fp16 epilogue staging for fp16-out modes.
// MODE: 1=bias+res fp32; 2=bias+gelu fp16; 3=bias fp16.
// ---------------------------------------------------------------------------
#define HSTAGE 32768
#define HSMEM  (3*HSTAGE)

template<int MODE>
__global__ __launch_bounds__(256, 2) void hgemm(
    const __half* __restrict__ A, const __half* __restrict__ B,
    const float* __restrict__ bias, const float* __restrict__ res,
    void* __restrict__ Cout, int N, int K)
{
    extern __shared__ char sm[];
    const uint32_t sbase = smem_u32(sm);
    const int tid  = threadIdx.x;
    const int lane = tid & 31;
    const int warp = tid >> 5;
    const int wr   = warp >> 1;
    const int wc   = warp & 1;
    const size_t gr0 = (size_t)blockIdx.y * 128;
    const int    gc0 = blockIdx.x * 128;
    const int CCH = K >> 6;

    const int lrow = tid >> 3;
    const int lkc  = tid & 7;

    auto load_stage = [&](int c) {
        uint32_t sA = sbase + (c % 3) * HSTAGE;
        uint32_t sB = sA + 16384;
        const __half* Ab = A + c*64 + lkc*8;
        const __half* Bb = B + c*64 + lkc*8;
        #pragma unroll
        for (int p = 0; p < 4; p++) {
            int row = lrow + p*32;
            uint32_t off = row*128 + (((uint32_t)(lkc ^ (row & 7))) << 4);
            CP_ASYNC16(sA + off, Ab + (gr0 + row) * (size_t)K);
            CP_ASYNC16(sB + off, Bb + (size_t)(gc0 + row) * K);
        }
    };

    load_stage(0); CP_COMMIT();
    load_stage(1); CP_COMMIT();

    float acc[2][8][4];
    #pragma unroll
    for (int mt = 0; mt < 2; mt++)
        #pragma unroll
        for (int nt = 0; nt < 8; nt++)
            #pragma unroll
            for (int q = 0; q < 4; q++) acc[mt][nt][q] = 0.0f;

    const int lr8  = (lane & 7) + ((lane >> 3) & 1) * 8;
    const int lkhi = lane >> 4;

    for (int c = 0; c < CCH; c++) {
        CP_WAIT1();
        __syncthreads();
        if (c + 2 < CCH) load_stage(c + 2);
        CP_COMMIT();

        uint32_t sA = sbase + (c % 3) * HSTAGE;
        uint32_t sB = sA + 16384;

        #pragma unroll
        for (int ks = 0; ks < 4; ks++) {
            int kc = 2*ks + lkhi;
            uint32_t a[2][4];
            #pragma unroll
            for (int mt = 0; mt < 2; mt++) {
                int row = wr*32 + mt*16 + lr8;
                LDSM_X4(a[mt][0], a[mt][1], a[mt][2], a[mt][3],
                        sA + row*128 + ((uint32_t)(kc ^ (row & 7)) << 4));
            }
            uint32_t b[4][4];
            #pragma unroll
            for (int nq = 0; nq < 4; nq++) {
                int row = wc*64 + nq*16 + lr8;
                LDSM_X4(b[nq][0], b[nq][1], b[nq][2], b[nq][3],
                        sB + row*128 + ((uint32_t)(kc ^ (row & 7)) << 4));
            }
            #pragma unroll
            for (int mt = 0; mt < 2; mt++)
                #pragma unroll
                for (int nt = 0; nt < 8; nt++)
                    MMA16816(acc[mt][nt], a[mt], b[nt>>1][nt&1], b[nt>>1][2+(nt&1)]);
        }
    }

    CP_WAIT0();
    __syncthreads();
    const int mrow = lane >> 2;
    const int ncol = (lane & 3) * 2;

    if (MODE == 2 || MODE == 3) {
        // ---- fp16 staging: bias(+gelu) in fragment space, 8-iter store ----
        __half* epi = (__half*)sm;              // 128 x 136 halves = 34 KB
        float2 bias2[8];
        #pragma unroll
        for (int nt = 0; nt < 8; nt++)
            bias2[nt] = *(const float2*)(bias + gc0 + wc*64 + nt*8 + ncol);
        #pragma unroll
        for (int mt = 0; mt < 2; mt++)
            #pragma unroll
            for (int half = 0; half < 2; half++) {
                int r = wr*32 + mt*16 + half*8 + mrow;
                #pragma unroll
                for (int nt = 0; nt < 8; nt++) {
                    int cc = wc*64 + nt*8 + ncol;
                    float v0 = acc[mt][nt][half*2]   + bias2[nt].x;
                    float v1 = acc[mt][nt][half*2+1] + bias2[nt].y;
                    if (MODE == 2) { v0 = gelu_f(v0); v1 = gelu_f(v1); }
                    *(uint32_t*)&epi[r*136 + cc] = pack_h2(v0, v1);
                }
            }
        __syncthreads();
        #pragma unroll
        for (int it = 0; it < 8; it++) {
            int idx = it*256 + tid;
            int row = idx >> 4;
            int c8  = (idx & 15) * 8;
            uint4 v = *(uint4*)&epi[row*136 + c8];
            *(uint4*)((__half*)Cout + (gr0 + row) * (size_t)N + gc0 + c8) = v;
        }
    } else {
        // ---- fp32 staging with residual (MODE 1) ----
        float* epi = (float*)sm;
        #pragma unroll
        for (int mt = 0; mt < 2; mt++)
            #pragma unroll
            for (int half = 0; half < 2; half++) {
                int r = wr*32 + mt*16 + half*8 + mrow;
                #pragma unroll
                for (int nt = 0; nt < 8; nt++) {
                    int cc = wc*64 + nt*8 + ncol;
                    *(float2*)&epi[r*132 + cc] =
                        make_float2(acc[mt][nt][half*2], acc[mt][nt][half*2+1]);
                }
            }
        __syncthreads();
        #pragma unroll 4
        for (int it = 0; it < 16; it++) {
            int idx = it*256 + tid;
            int row = idx >> 5;
            int c4  = (idx & 31) * 4;
            int gcol = gc0 + c4;
            float4 v = *(float4*)&epi[row*132 + c4];
            float4 bb = *(const float4*)(bias + gcol);
            v.x += bb.x; v.y += bb.y; v.z += bb.z; v.w += bb.w;
            size_t grow = gr0 + row;
            float4 r = *(const float4*)(res + grow * (size_t)N + gcol);
            v.x += r.x; v.y += r.y; v.z += r.z; v.w += r.w;
            *(float4*)((float*)Cout + grow * (size_t)N + gcol) = v;
        }
    }
}

// ---------------------------------------------------------------------------
// Fused shifted-window attention via mma.sync fp16 (R9/R11 1-head version).
// ---------------------------------------------------------------------------
__global__ __launch_bounds__(128) void attn_kernel(
    const __half* __restrict__ qkv, const __half* __restrict__ cb,
    __half* __restrict__ aoi)
{
    __shared__ __align__(16) __half qk_s[64*64];
    __shared__ __align__(16) __half v_s[32*64];
    __shared__ __align__(16) __half cb_s[64*64];

    const int head = blockIdx.x;
    const int w    = blockIdx.y;
    const int bimg = w >> 8;
    const int wimg = w & 255;
    const int wh   = wimg >> 4;
    const int ww   = wimg & 15;
    const int tid  = threadIdx.x;
    const int lane = tid & 31;
    const int wp   = tid >> 5;
    const uint32_t qkb = smem_u32(qk_s), vb = smem_u32(v_s);
    const float scale = 0.17677669529663689f;

    {
        const uint4* src = (const uint4*)(cb + ((size_t)wimg*8 + head)*4096);
        uint4* dst = (uint4*)cb_s;
        #pragma unroll
        for (int i = 0; i < 4; i++) dst[tid + 128*i] = src[tid + 128*i];
    }

    {
        const int dp = (tid & 15) * 2;
        const uint32_t ch = dp >> 3;
        const uint32_t wi = (dp & 7) * 2;
        #pragma unroll
        for (int it = 0; it < 8; it++) {
            int r = (tid >> 4) + 8*it;
            int i = r >> 3, j = r & 7;
            int oh = (wh*8 + i + 4) & 127;
            int ow = (ww*8 + j + 4) & 127;
            size_t tok = (size_t)bimg*16384 + oh*128 + ow;
            const __half* src = qkv + tok*768 + head*32 + dp;
            __half2 qh = *(const __half2*)(src);
            __half2 kh = *(const __half2*)(src + 256);
            __half2 vh = *(const __half2*)(src + 512);
            float2 qf = __half22float2(qh);
            uint32_t qp = pack_h2(qf.x * scale, qf.y * scale);
            uint32_t qa = r*128 + ((ch ^ (uint32_t)(r&7))<<4) + wi;
            uint32_t ka = r*128 + (((ch+4) ^ (uint32_t)(r&7))<<4) + wi;
            *(uint32_t*)((char*)qk_s + qa) = qp;
            *(uint32_t*)((char*)qk_s + ka) = *(uint32_t*)&kh;
            uint32_t va0 = dp*128     + ((uint32_t)((r>>3) ^ (dp&7))    <<4) + (r&7)*2;
            uint32_t va1 = (dp+1)*128 + ((uint32_t)((r>>3) ^ ((dp+1)&7))<<4) + (r&7)*2;
            *(__half*)((char*)v_s + va0) = __low2half(vh);
            *(__half*)((char*)v_s + va1) = __high2half(vh);
        }
    }
    __syncthreads();

    const int lr8  = (lane & 7) + ((lane >> 3) & 1) * 8;
    const int lkhi = lane >> 4;

    float acc[8][4];
    #pragma unroll
    for (int nt = 0; nt < 8; nt++)
        #pragma unroll
        for (int q = 0; q < 4; q++) acc[nt][q] = 0.0f;

    #pragma unroll
    for (int ks = 0; ks < 2; ks++) {
        int arow = wp*16 + lr8;
        int kcq  = 2*ks + lkhi;
        uint32_t a[4];
        LDSM_X4(a[0], a[1], a[2], a[3],
                qkb + arow*128 + ((uint32_t)(kcq ^ (arow & 7)) << 4));
        uint32_t b[4][4];
        #pragma unroll
        for (int nq = 0; nq < 4; nq++) {
            int brow = nq*16 + lr8;
            int kck  = 4 + 2*ks + lkhi;
            LDSM_X4(b[nq][0], b[nq][1], b[nq][2], b[nq][3],
                    qkb + brow*128 + ((uint32_t)(kck ^ (brow & 7)) << 4));
        }
        #pragma unroll
        for (int nt = 0; nt < 8; nt++)
            MMA16816(acc[nt], a, b[nt>>1][nt&1], b[nt>>1][2+(nt&1)]);
    }

    const int r0 = wp*16 + (lane >> 2);
    const int r1 = r0 + 8;
    const int mcol = (lane & 3) * 2;
    float mx0 = -1e30f, mx1 = -1e30f;
    #pragma unroll
    for (int nt = 0; nt < 8; nt++) {
        __half2 c0 = *(__half2*)&cb_s[r0*64 + nt*8 + mcol];
        __half2 c1 = *(__half2*)&cb_s[r1*64 + nt*8 + mcol];
        float2 f0 = __half22float2(c0);
        float2 f1 = __half22float2(c1);
        acc[nt][0] += f0.x; acc[nt][1] += f0.y;
        acc[nt][2] += f1.x; acc[nt][3] += f1.y;
        mx0 = fmaxf(mx0, fmaxf(acc[nt][0], acc[nt][1]));
        mx1 = fmaxf(mx1, fmaxf(acc[nt][2], acc[nt][3]));
    }
    mx0 = fmaxf(mx0, __shfl_xor_sync(0xffffffffu, mx0, 1));
    mx0 = fmaxf(mx0, __shfl_xor_sync(0xffffffffu, mx0, 2));
    mx1 = fmaxf(mx1, __shfl_xor_sync(0xffffffffu, mx1, 1));
    mx1 = fmaxf(mx1, __shfl_xor_sync(0xffffffffu, mx1, 2));
    float s0 = 0.0f, s1 = 0.0f;
    #pragma unroll
    for (int nt = 0; nt < 8; nt++) {
        acc[nt][0] = __expf(acc[nt][0] - mx0); s0 += acc[nt][0];
        acc[nt][1] = __expf(acc[nt][1] - mx0); s0 += acc[nt][1];
        acc[nt][2] = __expf(acc[nt][2] - mx1); s1 += acc[nt][2];
        acc[nt][3] = __expf(acc[nt][3] - mx1); s1 += acc[nt][3];
    }
    s0 += __shfl_xor_sync(0xffffffffu, s0, 1);
    s0 += __shfl_xor_sync(0xffffffffu, s0, 2);
    s1 += __shfl_xor_sync(0xffffffffu, s1, 1);
    s1 += __shfl_xor_sync(0xffffffffu, s1, 2);
    float inv0 = 1.0f / s0, inv1 = 1.0f / s1;

    float o[4][4];
    #pragma unroll
    for (int nt = 0; nt < 4; nt++)
        #pragma unroll
        for (int q = 0; q < 4; q++) o[nt][q] = 0.0f;

    #pragma unroll
    for (int kt = 0; kt < 4; kt++) {
        uint32_t a[4];
        a[0] = pack_h2(acc[2*kt][0]*inv0,   acc[2*kt][1]*inv0);
        a[1] = pack_h2(acc[2*kt][2]*inv1,   acc[2*kt][3]*inv1);
        a[2] = pack_h2(acc[2*kt+1][0]*inv0, acc[2*kt+1][1]*inv0);
        a[3] = pack_h2(acc[2*kt+1][2]*inv1, acc[2*kt+1][3]*inv1);
        uint32_t b[2][4];
        #pragma unroll
        for (int nq = 0; nq < 2; nq++) {
            int brow = nq*16 + lr8;
            int kc   = 2*kt + lkhi;
            LDSM_X4(b[nq][0], b[nq][1], b[nq][2], b[nq][3],
                    vb + brow*128 + ((uint32_t)(kc ^ (brow & 7)) << 4));
        }
        #pragma unroll
        for (int nt = 0; nt < 4; nt++)
            MMA16816(o[nt], a, b[nt>>1][nt&1], b[nt>>1][2+(nt&1)]);
    }

    #pragma unroll
    for (int s = 0; s < 2; s++) {
        int n = s ? r1 : r0;
        int i = n >> 3, j = n & 7;
        int oh = (wh*8 + i + 4) & 127;
        int ow = (ww*8 + j + 4) & 127;
        size_t tok = (size_t)bimg*16384 + oh*128 + ow;
        __half* base = aoi + tok*256 + head*32;
        #pragma unroll
        for (int nt = 0; nt < 4; nt++) {
            int c = nt*8 + (lane & 3)*2;
            *(uint32_t*)(base + c) = pack_h2(o[nt][s*2], o[nt][s*2+1]);
        }
    }
}

// ---------------------------------------------------------------------------
extern "C" void kernel_launch(void* const* d_in, const int* in_sizes, int n_in,
                              void* d_out, int out_size)
{
    const float* x     = (const float*)d_in[0];
    const float* mask  = (const float*)d_in[1];
    const float* n1g   = (const float*)d_in[2];
    const float* n1b   = (const float*)d_in[3];
    const float* qkvw  = (const float*)d_in[4];
    const float* qkvb  = (const float*)d_in[5];
    const float* relb  = (const float*)d_in[6];
    const float* projw = (const float*)d_in[7];
    const float* projb = (const float*)d_in[8];
    const float* n2g   = (const float*)d_in[9];
    const float* n2b   = (const float*)d_in[10];
    const float* fc1w  = (const float*)d_in[11];
    const float* fc1b  = (const float*)d_in[12];
    const float* fc2w  = (const float*)d_in[13];
    const float* fc2b  = (const float*)d_in[14];
    float* out = (float*)d_out;

    __half *xni, *qkv, *aoi, *hidi, *qkvwi, *projwi, *fc1wi, *fc2wi, *cb;
    float *x2;
    cudaGetSymbolAddress((void**)&xni,   g_xni);
    cudaGetSymbolAddress((void**)&qkv,   g_qkv);
    cudaGetSymbolAddress((void**)&aoi,   g_aoi);
    cudaGetSymbolAddress((void**)&x2,    g_x2);
    cudaGetSymbolAddress((void**)&hidi,  g_hidi);
    cudaGetSymbolAddress((void**)&qkvwi, g_qkvwi);
    cudaGetSymbolAddress((void**)&projwi,g_projwi);
    cudaGetSymbolAddress((void**)&fc1wi, g_fc1wi);
    cudaGetSymbolAddress((void**)&fc2wi, g_fc2wi);
    cudaGetSymbolAddress((void**)&cb,    g_cb);

    cudaFuncSetAttribute(hgemm<1>, cudaFuncAttributeMaxDynamicSharedMemorySize, HSMEM);
    cudaFuncSetAttribute(hgemm<2>, cudaFuncAttributeMaxDynamicSharedMemorySize, HSMEM);
    cudaFuncSetAttribute(hgemm<3>, cudaFuncAttributeMaxDynamicSharedMemorySize, HSMEM);

    wconv_all<<<768, 256>>>(qkvw, qkvwi, projw, projwi, fc1w, fc1wi, fc2w, fc2wi);
    cb_prep<<<16384, 256>>>(relb, mask, cb);

    // 1. LN1 -> fp16
    ln_kernel<<<MT/8, 256>>>(x, n1g, n1b, xni);
    // 2. QKV: [131072,256] @ [768,256]^T -> fp16
    hgemm<3><<<dim3(6, MT/128), 256, HSMEM>>>(xni, qkvwi, qkvb, nullptr, qkv, 768, 256);
    // 3. windowed attention (tensor-core)
    attn_kernel<<<dim3(8, 2048), 128>>>(qkv, cb, aoi);
    // 4. proj + residual(x) -> x2 fp32
    hgemm<1><<<dim3(2, MT/128), 256, HSMEM>>>(aoi, projwi, projb, x, x2, 256, 256);
    // 5. LN2 -> fp16
    ln_kernel<<<MT/8, 256>>>(x2, n2g, n2b, xni);
    // 6. FC1 + gelu -> fp16 hidden
    hgemm<2><<<dim3(8, MT/128), 256, HSMEM>>>(xni, fc1wi, fc1b, nullptr, hidi, 1024, 256);
    // 7. FC2 + residual(x2) -> out fp32
    hgemm<1><<<dim3(2, MT/128), 256, HSMEM>>>(hidi, fc2wi, fc2b, x2, out, 256, 1024);
}

// round 16
// speedup vs baseline: 1.0195x; 1.0065x over previous
#include <cuda_runtime.h>
#include <cuda_fp16.h>
#include <cstdint>
#include <cmath>

// ===========================================================================
// SwinTransformerBlock on GB300 (family-portable PTX, mma.sync fp16).
// R16 = R15 (best: fp16-staged GEMM epilogues) + attention change:
// bias+mask (cb) loaded DIRECTLY into per-thread registers at gather time
// (latency overlapped with score MMAs); cb_s smem buffer and staging loop
// removed (attn smem 20 KB -> 12 KB).
// ===========================================================================

#define MT 131072

__device__ __align__(16) __half g_xni [(size_t)MT*256];
__device__ __align__(16) __half g_qkv [(size_t)MT*768];
__device__ __align__(16) __half g_aoi [(size_t)MT*256];
__device__ float                g_x2  [(size_t)MT*256];
__device__ __align__(16) __half g_hidi[(size_t)MT*1024];
__device__ __align__(16) __half g_qkvwi[768*256];
__device__ __align__(16) __half g_projwi[256*256];
__device__ __align__(16) __half g_fc1wi[1024*256];
__device__ __align__(16) __half g_fc2wi[256*1024];
__device__ __align__(16) __half g_cb  [256*8*4096];

// ---------------------------------------------------------------------------
__device__ __forceinline__ uint32_t smem_u32(const void* p) {
    uint32_t a;
    asm("{ .reg .u64 t; cvta.to.shared.u64 t, %1; cvt.u32.u64 %0, t; }" : "=r"(a) : "l"(p));
    return a;
}
#define CP_ASYNC16(sa, ga) \
    asm volatile("cp.async.cg.shared.global [%0], [%1], 16;" :: "r"(sa), "l"(ga))
#define CP_COMMIT() asm volatile("cp.async.commit_group;" ::: "memory")
#define CP_WAIT1()  asm volatile("cp.async.wait_group 1;" ::: "memory")
#define CP_WAIT0()  asm volatile("cp.async.wait_group 0;" ::: "memory")

#define LDSM_X4(r0,r1,r2,r3, a) \
    asm volatile("ldmatrix.sync.aligned.m8n8.x4.shared.b16 {%0,%1,%2,%3}, [%4];" \
        : "=r"(r0), "=r"(r1), "=r"(r2), "=r"(r3) : "r"(a))

#define MMA16816(c, a, b0, b1) \
    asm volatile("mma.sync.aligned.m16n8k16.row.col.f32.f16.f16.f32 " \
        "{%0,%1,%2,%3}, {%4,%5,%6,%7}, {%8,%9}, {%0,%1,%2,%3};" \
        : "+f"((c)[0]), "+f"((c)[1]), "+f"((c)[2]), "+f"((c)[3]) \
        : "r"((a)[0]), "r"((a)[1]), "r"((a)[2]), "r"((a)[3]), "r"(b0), "r"(b1))

__device__ __forceinline__ uint32_t pack_h2(float a, float b) {
    __half2 t = __floats2half2_rn(a, b);
    return *(uint32_t*)&t;
}
__device__ __forceinline__ uint2 pack_h4(float4 v) {
    uint2 u;
    u.x = pack_h2(v.x, v.y);
    u.y = pack_h2(v.z, v.w);
    return u;
}
__device__ __forceinline__ float gelu_f(float v) {
    return 0.5f * v * (1.0f + erff(v * 0.7071067811865476f));
}

// ---------------------------------------------------------------------------
// Combined weight conversion: fp32 [N,K] -> fp16 [N,K]
// ---------------------------------------------------------------------------
__global__ void wconv_all(const float* w0, __half* o0,
                          const float* w1, __half* o1,
                          const float* w2, __half* o2,
                          const float* w3, __half* o3) {
    int i = blockIdx.x * 256 + threadIdx.x;
    const float* w; __half* o; int li;
    if (i < 49152)        { w = w0; o = o0; li = i; }
    else if (i < 65536)   { w = w1; o = o1; li = i - 49152; }
    else if (i < 131072)  { w = w2; o = o2; li = i - 65536; }
    else if (i < 196608)  { w = w3; o = o3; li = i - 131072; }
    else return;
    float4 v = *(const float4*)(w + (size_t)li * 4);
    *(uint2*)(o + (size_t)li * 4) = pack_h4(v);
}

// ---------------------------------------------------------------------------
// Combined bias+mask table (fp16)
// ---------------------------------------------------------------------------
__global__ void cb_prep(const float* __restrict__ bt, const float* __restrict__ mask,
                        __half* __restrict__ cb) {
    int lin = blockIdx.x * 256 + threadIdx.x;
    int m    = (lin & 31) * 2;
    int n    = (lin >> 5) & 63;
    int head = (lin >> 11) & 7;
    int wimg = lin >> 14;
    float mk0 = mask[wimg*4096 + n*64 + m];
    float mk1 = mask[wimg*4096 + n*64 + m + 1];
    int ri0 = ((n>>3) - (m>>3) + 7)*15 + ((n&7) - (m&7) + 7);
    int ri1 = ((n>>3) - ((m+1)>>3) + 7)*15 + ((n&7) - ((m+1)&7) + 7);
    float b0 = bt[ri0*8 + head] + mk0;
    float b1 = bt[ri1*8 + head] + mk1;
    *(uint32_t*)(cb + (size_t)lin * 2) = pack_h2(b0, b1);
}

// ---------------------------------------------------------------------------
// LayerNorm (C=256): one warp/row, fp16 out
// ---------------------------------------------------------------------------
__global__ __launch_bounds__(256) void ln_kernel(
    const float* __restrict__ x, const float* __restrict__ g,
    const float* __restrict__ b, __half* __restrict__ out)
{
    size_t row = (size_t)blockIdx.x * 8 + (threadIdx.x >> 5);
    int lane = threadIdx.x & 31;
    const float* xr = x + row * 256 + lane * 8;
    float4 v0 = *(const float4*)(xr);
    float4 v1 = *(const float4*)(xr + 4);

    float s  = v0.x+v0.y+v0.z+v0.w + v1.x+v1.y+v1.z+v1.w;
    float sq = v0.x*v0.x+v0.y*v0.y+v0.z*v0.z+v0.w*v0.w
             + v1.x*v1.x+v1.y*v1.y+v1.z*v1.z+v1.w*v1.w;
    #pragma unroll
    for (int o = 16; o > 0; o >>= 1) {
        s  += __shfl_xor_sync(0xffffffffu, s,  o);
        sq += __shfl_xor_sync(0xffffffffu, sq, o);
    }
    float mean = s * (1.0f/256.0f);
    float rstd = rsqrtf(sq * (1.0f/256.0f) - mean*mean + 1e-5f);

    const float4 g0 = *(const float4*)(g + lane*8);
    const float4 g1 = *(const float4*)(g + lane*8 + 4);
    const float4 b0 = *(const float4*)(b + lane*8);
    const float4 b1 = *(const float4*)(b + lane*8 + 4);

    float4 o0, o1;
    o0.x=(v0.x-mean)*rstd*g0.x+b0.x; o0.y=(v0.y-mean)*rstd*g0.y+b0.y;
    o0.z=(v0.z-mean)*rstd*g0.z+b0.z; o0.w=(v0.w-mean)*rstd*g0.w+b0.w;
    o1.x=(v1.x-mean)*rstd*g1.x+b1.x; o1.y=(v1.y-mean)*rstd*g1.y+b1.y;
    o1.z=(v1.z-mean)*rstd*g1.z+b1.z; o1.w=(v1.w-mean)*rstd*g1.w+b1.w;

    uint4 u;
    u.x = pack_h2(o0.x, o0.y); u.y = pack_h2(o0.z, o0.w);
    u.z = pack_h2(o1.x, o1.y); u.w = pack_h2(o1.z, o1.w);
    *(uint4*)(out + row * 256 + lane * 8) = u;
}

// ---------------------------------------------------------------------------
// fp16 tensor-core GEMM: CTA 128x128, warp 32x64, 3-stage cp.async,
// 2 CTAs/SM, one sync per chunk. fp16 epilogue staging for fp16-out modes.
// MODE: 1=bias+res fp32; 2=bias+gelu fp16; 3=bias fp16.
// ---------------------------------------------------------------------------
#define HSTAGE 32768
#define HSMEM  (3*HSTAGE)

template<int MODE>
__global__ __launch_bounds__(256, 2) void hgemm(
    const __half* __restrict__ A, const __half* __restrict__ B,
    const float* __restrict__ bias, const float* __restrict__ res,
    void* __restrict__ Cout, int N, int K)
{
    extern __shared__ char sm[];
    const uint32_t sbase = smem_u32(sm);
    const int tid  = threadIdx.x;
    const int lane = tid & 31;
    const int warp = tid >> 5;
    const int wr   = warp >> 1;
    const int wc   = warp & 1;
    const size_t gr0 = (size_t)blockIdx.y * 128;
    const int    gc0 = blockIdx.x * 128;
    const int CCH = K >> 6;

    const int lrow = tid >> 3;
    const int lkc  = tid & 7;

    auto load_stage = [&](int c) {
        uint32_t sA = sbase + (c % 3) * HSTAGE;
        uint32_t sB = sA + 16384;
        const __half* Ab = A + c*64 + lkc*8;
        const __half* Bb = B + c*64 + lkc*8;
        #pragma unroll
        for (int p = 0; p < 4; p++) {
            int row = lrow + p*32;
            uint32_t off = row*128 + (((uint32_t)(lkc ^ (row & 7))) << 4);
            CP_ASYNC16(sA + off, Ab + (gr0 + row) * (size_t)K);
            CP_ASYNC16(sB + off, Bb + (size_t)(gc0 + row) * K);
        }
    };

    load_stage(0); CP_COMMIT();
    load_stage(1); CP_COMMIT();

    float acc[2][8][4];
    #pragma unroll
    for (int mt = 0; mt < 2; mt++)
        #pragma unroll
        for (int nt = 0; nt < 8; nt++)
            #pragma unroll
            for (int q = 0; q < 4; q++) acc[mt][nt][q] = 0.0f;

    const int lr8  = (lane & 7) + ((lane >> 3) & 1) * 8;
    const int lkhi = lane >> 4;

    for (int c = 0; c < CCH; c++) {
        CP_WAIT1();
        __syncthreads();
        if (c + 2 < CCH) load_stage(c + 2);
        CP_COMMIT();

        uint32_t sA = sbase + (c % 3) * HSTAGE;
        uint32_t sB = sA + 16384;

        #pragma unroll
        for (int ks = 0; ks < 4; ks++) {
            int kc = 2*ks + lkhi;
            uint32_t a[2][4];
            #pragma unroll
            for (int mt = 0; mt < 2; mt++) {
                int row = wr*32 + mt*16 + lr8;
                LDSM_X4(a[mt][0], a[mt][1], a[mt][2], a[mt][3],
                        sA + row*128 + ((uint32_t)(kc ^ (row & 7)) << 4));
            }
            uint32_t b[4][4];
            #pragma unroll
            for (int nq = 0; nq < 4; nq++) {
                int row = wc*64 + nq*16 + lr8;
                LDSM_X4(b[nq][0], b[nq][1], b[nq][2], b[nq][3],
                        sB + row*128 + ((uint32_t)(kc ^ (row & 7)) << 4));
            }
            #pragma unroll
            for (int mt = 0; mt < 2; mt++)
                #pragma unroll
                for (int nt = 0; nt < 8; nt++)
                    MMA16816(acc[mt][nt], a[mt], b[nt>>1][nt&1], b[nt>>1][2+(nt&1)]);
        }
    }

    CP_WAIT0();
    __syncthreads();
    const int mrow = lane >> 2;
    const int ncol = (lane & 3) * 2;

    if (MODE == 2 || MODE == 3) {
        __half* epi = (__half*)sm;
        float2 bias2[8];
        #pragma unroll
        for (int nt = 0; nt < 8; nt++)
            bias2[nt] = *(const float2*)(bias + gc0 + wc*64 + nt*8 + ncol);
        #pragma unroll
        for (int mt = 0; mt < 2; mt++)
            #pragma unroll
            for (int half = 0; half < 2; half++) {
                int r = wr*32 + mt*16 + half*8 + mrow;
                #pragma unroll
                for (int nt = 0; nt < 8; nt++) {
                    int cc = wc*64 + nt*8 + ncol;
                    float v0 = acc[mt][nt][half*2]   + bias2[nt].x;
                    float v1 = acc[mt][nt][half*2+1] + bias2[nt].y;
                    if (MODE == 2) { v0 = gelu_f(v0); v1 = gelu_f(v1); }
                    *(uint32_t*)&epi[r*136 + cc] = pack_h2(v0, v1);
                }
            }
        __syncthreads();
        #pragma unroll
        for (int it = 0; it < 8; it++) {
            int idx = it*256 + tid;
            int row = idx >> 4;
            int c8  = (idx & 15) * 8;
            uint4 v = *(uint4*)&epi[row*136 + c8];
            *(uint4*)((__half*)Cout + (gr0 + row) * (size_t)N + gc0 + c8) = v;
        }
    } else {
        float* epi = (float*)sm;
        #pragma unroll
        for (int mt = 0; mt < 2; mt++)
            #pragma unroll
            for (int half = 0; half < 2; half++) {
                int r = wr*32 + mt*16 + half*8 + mrow;
                #pragma unroll
                for (int nt = 0; nt < 8; nt++) {
                    int cc = wc*64 + nt*8 + ncol;
                    *(float2*)&epi[r*132 + cc] =
                        make_float2(acc[mt][nt][half*2], acc[mt][nt][half*2+1]);
                }
            }
        __syncthreads();
        #pragma unroll 4
        for (int it = 0; it < 16; it++) {
            int idx = it*256 + tid;
            int row = idx >> 5;
            int c4  = (idx & 31) * 4;
            int gcol = gc0 + c4;
            float4 v = *(float4*)&epi[row*132 + c4];
            float4 bb = *(const float4*)(bias + gcol);
            v.x += bb.x; v.y += bb.y; v.z += bb.z; v.w += bb.w;
            size_t grow = gr0 + row;
            float4 r = *(const float4*)(res + grow * (size_t)N + gcol);
            v.x += r.x; v.y += r.y; v.z += r.z; v.w += r.w;
            *(float4*)((float*)Cout + grow * (size_t)N + gcol) = v;
        }
    }
}

// ---------------------------------------------------------------------------
// Fused shifted-window attention via mma.sync fp16.
// R16: cb (bias+mask) loaded directly into registers (overlapped w/ MMAs);
// no cb_s smem buffer.
// ---------------------------------------------------------------------------
__global__ __launch_bounds__(128) void attn_kernel(
    const __half* __restrict__ qkv, const __half* __restrict__ cb,
    __half* __restrict__ aoi)
{
    __shared__ __align__(16) __half qk_s[64*64];
    __shared__ __align__(16) __half v_s[32*64];

    const int head = blockIdx.x;
    const int w    = blockIdx.y;
    const int bimg = w >> 8;
    const int wimg = w & 255;
    const int wh   = wimg >> 4;
    const int ww   = wimg & 15;
    const int tid  = threadIdx.x;
    const int lane = tid & 31;
    const int wp   = tid >> 5;
    const uint32_t qkb = smem_u32(qk_s), vb = smem_u32(v_s);
    const float scale = 0.17677669529663689f;

    // ---- gather q,k,v into smem ----
    {
        const int dp = (tid & 15) * 2;
        const uint32_t ch = dp >> 3;
        const uint32_t wi = (dp & 7) * 2;
        #pragma unroll
        for (int it = 0; it < 8; it++) {
            int r = (tid >> 4) + 8*it;
            int i = r >> 3, j = r & 7;
            int oh = (wh*8 + i + 4) & 127;
            int ow = (ww*8 + j + 4) & 127;
            size_t tok = (size_t)bimg*16384 + oh*128 + ow;
            const __half* src = qkv + tok*768 + head*32 + dp;
            __half2 qh = *(const __half2*)(src);
            __half2 kh = *(const __half2*)(src + 256);
            __half2 vh = *(const __half2*)(src + 512);
            float2 qf = __half22float2(qh);
            uint32_t qp = pack_h2(qf.x * scale, qf.y * scale);
            uint32_t qa = r*128 + ((ch ^ (uint32_t)(r&7))<<4) + wi;
            uint32_t ka = r*128 + (((ch+4) ^ (uint32_t)(r&7))<<4) + wi;
            *(uint32_t*)((char*)qk_s + qa) = qp;
            *(uint32_t*)((char*)qk_s + ka) = *(uint32_t*)&kh;
            uint32_t va0 = dp*128     + ((uint32_t)((r>>3) ^ (dp&7))    <<4) + (r&7)*2;
            uint32_t va1 = (dp+1)*128 + ((uint32_t)((r>>3) ^ ((dp+1)&7))<<4) + (r&7)*2;
            *(__half*)((char*)v_s + va0) = __low2half(vh);
            *(__half*)((char*)v_s + va1) = __high2half(vh);
        }
    }

    // ---- prefetch cb for this thread's fragment rows (overlaps with MMAs) --
    const int r0 = wp*16 + (lane >> 2);
    const int r1 = r0 + 8;
    const int mcol = (lane & 3) * 2;
    __half2 cbr0[8], cbr1[8];
    {
        const __half* cbp = cb + ((size_t)wimg*8 + head)*4096;
        #pragma unroll
        for (int nt = 0; nt < 8; nt++) {
            cbr0[nt] = *(const __half2*)&cbp[r0*64 + nt*8 + mcol];
            cbr1[nt] = *(const __half2*)&cbp[r1*64 + nt*8 + mcol];
        }
    }
    __syncthreads();

    const int lr8  = (lane & 7) + ((lane >> 3) & 1) * 8;
    const int lkhi = lane >> 4;

    // ---- scores ----
    float acc[8][4];
    #pragma unroll
    for (int nt = 0; nt < 8; nt++)
        #pragma unroll
        for (int q = 0; q < 4; q++) acc[nt][q] = 0.0f;

    #pragma unroll
    for (int ks = 0; ks < 2; ks++) {
        int arow = wp*16 + lr8;
        int kcq  = 2*ks + lkhi;
        uint32_t a[4];
        LDSM_X4(a[0], a[1], a[2], a[3],
                qkb + arow*128 + ((uint32_t)(kcq ^ (arow & 7)) << 4));
        uint32_t b[4][4];
        #pragma unroll
        for (int nq = 0; nq < 4; nq++) {
            int brow = nq*16 + lr8;
            int kck  = 4 + 2*ks + lkhi;
            LDSM_X4(b[nq][0], b[nq][1], b[nq][2], b[nq][3],
                    qkb + brow*128 + ((uint32_t)(kck ^ (brow & 7)) << 4));
        }
        #pragma unroll
        for (int nt = 0; nt < 8; nt++)
            MMA16816(acc[nt], a, b[nt>>1][nt&1], b[nt>>1][2+(nt&1)]);
    }

    // ---- bias+mask (registers) + softmax ----
    float mx0 = -1e30f, mx1 = -1e30f;
    #pragma unroll
    for (int nt = 0; nt < 8; nt++) {
        float2 f0 = __half22float2(cbr0[nt]);
        float2 f1 = __half22float2(cbr1[nt]);
        acc[nt][0] += f0.x; acc[nt][1] += f0.y;
        acc[nt][2] += f1.x; acc[nt][3] += f1.y;
        mx0 = fmaxf(mx0, fmaxf(acc[nt][0], acc[nt][1]));
        mx1 = fmaxf(mx1, fmaxf(acc[nt][2], acc[nt][3]));
    }
    mx0 = fmaxf(mx0, __shfl_xor_sync(0xffffffffu, mx0, 1));
    mx0 = fmaxf(mx0, __shfl_xor_sync(0xffffffffu, mx0, 2));
    mx1 = fmaxf(mx1, __shfl_xor_sync(0xffffffffu, mx1, 1));
    mx1 = fmaxf(mx1, __shfl_xor_sync(0xffffffffu, mx1, 2));
    float s0 = 0.0f, s1 = 0.0f;
    #pragma unroll
    for (int nt = 0; nt < 8; nt++) {
        acc[nt][0] = __expf(acc[nt][0] - mx0); s0 += acc[nt][0];
        acc[nt][1] = __expf(acc[nt][1] - mx0); s0 += acc[nt][1];
        acc[nt][2] = __expf(acc[nt][2] - mx1); s1 += acc[nt][2];
        acc[nt][3] = __expf(acc[nt][3] - mx1); s1 += acc[nt][3];
    }
    s0 += __shfl_xor_sync(0xffffffffu, s0, 1);
    s0 += __shfl_xor_sync(0xffffffffu, s0, 2);
    s1 += __shfl_xor_sync(0xffffffffu, s1, 1);
    s1 += __shfl_xor_sync(0xffffffffu, s1, 2);
    float inv0 = 1.0f / s0, inv1 = 1.0f / s1;

    // ---- out = p @ v: register-built P fragments ----
    float o[4][4];
    #pragma unroll
    for (int nt = 0; nt < 4; nt++)
        #pragma unroll
        for (int q = 0; q < 4; q++) o[nt][q] = 0.0f;

    #pragma unroll
    for (int kt = 0; kt < 4; kt++) {
        uint32_t a[4];
        a[0] = pack_h2(acc[2*kt][0]*inv0,   acc[2*kt][1]*inv0);
        a[1] = pack_h2(acc[2*kt][2]*inv1,   acc[2*kt][3]*inv1);
        a[2] = pack_h2(acc[2*kt+1][0]*inv0, acc[2*kt+1][1]*inv0);
        a[3] = pack_h2(acc[2*kt+1][2]*inv1, acc[2*kt+1][3]*inv1);
        uint32_t b[2][4];
        #pragma unroll
        for (int nq = 0; nq < 2; nq++) {
            int brow = nq*16 + lr8;
            int kc   = 2*kt + lkhi;
            LDSM_X4(b[nq][0], b[nq][1], b[nq][2], b[nq][3],
                    vb + brow*128 + ((uint32_t)(kc ^ (brow & 7)) << 4));
        }
        #pragma unroll
        for (int nt = 0; nt < 4; nt++)
            MMA16816(o[nt], a, b[nt>>1][nt&1], b[nt>>1][2+(nt&1)]);
    }

    // ---- scatter out fp16 ----
    #pragma unroll
    for (int s = 0; s < 2; s++) {
        int n = s ? r1 : r0;
        int i = n >> 3, j = n & 7;
        int oh = (wh*8 + i + 4) & 127;
        int ow = (ww*8 + j + 4) & 127;
        size_t tok = (size_t)bimg*16384 + oh*128 + ow;
        __half* base = aoi + tok*256 + head*32;
        #pragma unroll
        for (int nt = 0; nt < 4; nt++) {
            int c = nt*8 + (lane & 3)*2;
            *(uint32_t*)(base + c) = pack_h2(o[nt][s*2], o[nt][s*2+1]);
        }
    }
}

// ---------------------------------------------------------------------------
extern "C" void kernel_launch(void* const* d_in, const int* in_sizes, int n_in,
                              void* d_out, int out_size)
{
    const float* x     = (const float*)d_in[0];
    const float* mask  = (const float*)d_in[1];
    const float* n1g   = (const float*)d_in[2];
    const float* n1b   = (const float*)d_in[3];
    const float* qkvw  = (const float*)d_in[4];
    const float* qkvb  = (const float*)d_in[5];
    const float* relb  = (const float*)d_in[6];
    const float* projw = (const float*)d_in[7];
    const float* projb = (const float*)d_in[8];
    const float* n2g   = (const float*)d_in[9];
    const float* n2b   = (const float*)d_in[10];
    const float* fc1w  = (const float*)d_in[11];
    const float* fc1b  = (const float*)d_in[12];
    const float* fc2w  = (const float*)d_in[13];
    const float* fc2b  = (const float*)d_in[14];
    float* out = (float*)d_out;

    __half *xni, *qkv, *aoi, *hidi, *qkvwi, *projwi, *fc1wi, *fc2wi, *cb;
    float *x2;
    cudaGetSymbolAddress((void**)&xni,   g_xni);
    cudaGetSymbolAddress((void**)&qkv,   g_qkv);
    cudaGetSymbolAddress((void**)&aoi,   g_aoi);
    cudaGetSymbolAddress((void**)&x2,    g_x2);
    cudaGetSymbolAddress((void**)&hidi,  g_hidi);
    cudaGetSymbolAddress((void**)&qkvwi, g_qkvwi);
    cudaGetSymbolAddress((void**)&projwi,g_projwi);
    cudaGetSymbolAddress((void**)&fc1wi, g_fc1wi);
    cudaGetSymbolAddress((void**)&fc2wi, g_fc2wi);
    cudaGetSymbolAddress((void**)&cb,    g_cb);

    cudaFuncSetAttribute(hgemm<1>, cudaFuncAttributeMaxDynamicSharedMemorySize, HSMEM);
    cudaFuncSetAttribute(hgemm<2>, cudaFuncAttributeMaxDynamicSharedMemorySize, HSMEM);
    cudaFuncSetAttribute(hgemm<3>, cudaFuncAttributeMaxDynamicSharedMemorySize, HSMEM);

    wconv_all<<<768, 256>>>(qkvw, qkvwi, projw, projwi, fc1w, fc1wi, fc2w, fc2wi);
    cb_prep<<<16384, 256>>>(relb, mask, cb);

    // 1. LN1 -> fp16
    ln_kernel<<<MT/8, 256>>>(x, n1g, n1b, xni);
    // 2. QKV: [131072,256] @ [768,256]^T -> fp16
    hgemm<3><<<dim3(6, MT/128), 256, HSMEM>>>(xni, qkvwi, qkvb, nullptr, qkv, 768, 256);
    // 3. windowed attention (tensor-core)
    attn_kernel<<<dim3(8, 2048), 128>>>(qkv, cb, aoi);
    // 4. proj + residual(x) -> x2 fp32
    hgemm<1><<<dim3(2, MT/128), 256, HSMEM>>>(aoi, projwi, projb, x, x2, 256, 256);
    // 5. LN2 -> fp16
    ln_kernel<<<MT/8, 256>>>(x2, n2g, n2b, xni);
    // 6. FC1 + gelu -> fp16 hidden
    hgemm<2><<<dim3(8, MT/128), 256, HSMEM>>>(xni, fc1wi, fc1b, nullptr, hidi, 1024, 256);
    // 7. FC2 + residual(x2) -> out fp32
    hgemm<1><<<dim3(2, MT/128), 256, HSMEM>>>(hidi, fc2wi, fc2b, x2, out, 256, 1024);
}

// round 17
// speedup vs baseline: 1.0328x; 1.0131x over previous
#include <cuda_runtime.h>
#include <cuda_fp16.h>
#include <cstdint>
#include <cmath>

// ===========================================================================
// SwinTransformerBlock on GB300 (family-portable PTX, mma.sync fp16).
// R17 = R16 + fp16 x2 residual buffer (precision-budget arbitrage):
//   proj: MODE 4 = bias + fp32-res -> fp16 out  (write 134->67 MB)
//   LN2:  fp16-input variant                     (read 134->67 MB)
//   FC2:  MODE 5 = bias + fp16-res -> fp32 out   (res read 134->67 MB)
// rel_err budget: 4.7e-5 -> ~2-3e-4 (threshold 1e-3).
// ===========================================================================

#define MT 131072

__device__ __align__(16) __half g_xni [(size_t)MT*256];
__device__ __align__(16) __half g_qkv [(size_t)MT*768];
__device__ __align__(16) __half g_aoi [(size_t)MT*256];
__device__ __align__(16) __half g_x2  [(size_t)MT*256];   // now fp16
__device__ __align__(16) __half g_hidi[(size_t)MT*1024];
__device__ __align__(16) __half g_qkvwi[768*256];
__device__ __align__(16) __half g_projwi[256*256];
__device__ __align__(16) __half g_fc1wi[1024*256];
__device__ __align__(16) __half g_fc2wi[256*1024];
__device__ __align__(16) __half g_cb  [256*8*4096];

// ---------------------------------------------------------------------------
__device__ __forceinline__ uint32_t smem_u32(const void* p) {
    uint32_t a;
    asm("{ .reg .u64 t; cvta.to.shared.u64 t, %1; cvt.u32.u64 %0, t; }" : "=r"(a) : "l"(p));
    return a;
}
#define CP_ASYNC16(sa, ga) \
    asm volatile("cp.async.cg.shared.global [%0], [%1], 16;" :: "r"(sa), "l"(ga))
#define CP_COMMIT() asm volatile("cp.async.commit_group;" ::: "memory")
#define CP_WAIT1()  asm volatile("cp.async.wait_group 1;" ::: "memory")
#define CP_WAIT0()  asm volatile("cp.async.wait_group 0;" ::: "memory")

#define LDSM_X4(r0,r1,r2,r3, a) \
    asm volatile("ldmatrix.sync.aligned.m8n8.x4.shared.b16 {%0,%1,%2,%3}, [%4];" \
        : "=r"(r0), "=r"(r1), "=r"(r2), "=r"(r3) : "r"(a))

#define MMA16816(c, a, b0, b1) \
    asm volatile("mma.sync.aligned.m16n8k16.row.col.f32.f16.f16.f32 " \
        "{%0,%1,%2,%3}, {%4,%5,%6,%7}, {%8,%9}, {%0,%1,%2,%3};" \
        : "+f"((c)[0]), "+f"((c)[1]), "+f"((c)[2]), "+f"((c)[3]) \
        : "r"((a)[0]), "r"((a)[1]), "r"((a)[2]), "r"((a)[3]), "r"(b0), "r"(b1))

__device__ __forceinline__ uint32_t pack_h2(float a, float b) {
    __half2 t = __floats2half2_rn(a, b);
    return *(uint32_t*)&t;
}
__device__ __forceinline__ uint2 pack_h4(float4 v) {
    uint2 u;
    u.x = pack_h2(v.x, v.y);
    u.y = pack_h2(v.z, v.w);
    return u;
}
__device__ __forceinline__ float gelu_f(float v) {
    return 0.5f * v * (1.0f + erff(v * 0.7071067811865476f));
}

// ---------------------------------------------------------------------------
// Combined weight conversion: fp32 [N,K] -> fp16 [N,K]
// ---------------------------------------------------------------------------
__global__ void wconv_all(const float* w0, __half* o0,
                          const float* w1, __half* o1,
                          const float* w2, __half* o2,
                          const float* w3, __half* o3) {
    int i = blockIdx.x * 256 + threadIdx.x;
    const float* w; __half* o; int li;
    if (i < 49152)        { w = w0; o = o0; li = i; }
    else if (i < 65536)   { w = w1; o = o1; li = i - 49152; }
    else if (i < 131072)  { w = w2; o = o2; li = i - 65536; }
    else if (i < 196608)  { w = w3; o = o3; li = i - 131072; }
    else return;
    float4 v = *(const float4*)(w + (size_t)li * 4);
    *(uint2*)(o + (size_t)li * 4) = pack_h4(v);
}

// ---------------------------------------------------------------------------
// Combined bias+mask table (fp16)
// ---------------------------------------------------------------------------
__global__ void cb_prep(const float* __restrict__ bt, const float* __restrict__ mask,
                        __half* __restrict__ cb) {
    int lin = blockIdx.x * 256 + threadIdx.x;
    int m    = (lin & 31) * 2;
    int n    = (lin >> 5) & 63;
    int head = (lin >> 11) & 7;
    int wimg = lin >> 14;
    float mk0 = mask[wimg*4096 + n*64 + m];
    float mk1 = mask[wimg*4096 + n*64 + m + 1];
    int ri0 = ((n>>3) - (m>>3) + 7)*15 + ((n&7) - (m&7) + 7);
    int ri1 = ((n>>3) - ((m+1)>>3) + 7)*15 + ((n&7) - ((m+1)&7) + 7);
    float b0 = bt[ri0*8 + head] + mk0;
    float b1 = bt[ri1*8 + head] + mk1;
    *(uint32_t*)(cb + (size_t)lin * 2) = pack_h2(b0, b1);
}

// ---------------------------------------------------------------------------
// LayerNorm core + fp32/fp16-input wrappers (one warp per 256-wide row)
// ---------------------------------------------------------------------------
__device__ __forceinline__ void ln_body(float4 v0, float4 v1,
                                        const float* g, const float* b,
                                        int lane, __half* orow) {
    float s  = v0.x+v0.y+v0.z+v0.w + v1.x+v1.y+v1.z+v1.w;
    float sq = v0.x*v0.x+v0.y*v0.y+v0.z*v0.z+v0.w*v0.w
             + v1.x*v1.x+v1.y*v1.y+v1.z*v1.z+v1.w*v1.w;
    #pragma unroll
    for (int o = 16; o > 0; o >>= 1) {
        s  += __shfl_xor_sync(0xffffffffu, s,  o);
        sq += __shfl_xor_sync(0xffffffffu, sq, o);
    }
    float mean = s * (1.0f/256.0f);
    float rstd = rsqrtf(sq * (1.0f/256.0f) - mean*mean + 1e-5f);

    const float4 g0 = *(const float4*)(g + lane*8);
    const float4 g1 = *(const float4*)(g + lane*8 + 4);
    const float4 b0 = *(const float4*)(b + lane*8);
    const float4 b1 = *(const float4*)(b + lane*8 + 4);

    float4 o0, o1;
    o0.x=(v0.x-mean)*rstd*g0.x+b0.x; o0.y=(v0.y-mean)*rstd*g0.y+b0.y;
    o0.z=(v0.z-mean)*rstd*g0.z+b0.z; o0.w=(v0.w-mean)*rstd*g0.w+b0.w;
    o1.x=(v1.x-mean)*rstd*g1.x+b1.x; o1.y=(v1.y-mean)*rstd*g1.y+b1.y;
    o1.z=(v1.z-mean)*rstd*g1.z+b1.z; o1.w=(v1.w-mean)*rstd*g1.w+b1.w;

    uint4 u;
    u.x = pack_h2(o0.x, o0.y); u.y = pack_h2(o0.z, o0.w);
    u.z = pack_h2(o1.x, o1.y); u.w = pack_h2(o1.z, o1.w);
    *(uint4*)orow = u;
}

__global__ __launch_bounds__(256) void ln_kernel_f32(
    const float* __restrict__ x, const float* __restrict__ g,
    const float* __restrict__ b, __half* __restrict__ out)
{
    size_t row = (size_t)blockIdx.x * 8 + (threadIdx.x >> 5);
    int lane = threadIdx.x & 31;
    const float* xr = x + row * 256 + lane * 8;
    float4 v0 = *(const float4*)(xr);
    float4 v1 = *(const float4*)(xr + 4);
    ln_body(v0, v1, g, b, lane, out + row * 256 + lane * 8);
}

__global__ __launch_bounds__(256) void ln_kernel_f16(
    const __half* __restrict__ x, const float* __restrict__ g,
    const float* __restrict__ b, __half* __restrict__ out)
{
    size_t row = (size_t)blockIdx.x * 8 + (threadIdx.x >> 5);
    int lane = threadIdx.x & 31;
    uint4 u = *(const uint4*)(x + row * 256 + lane * 8);
    float2 f0 = __half22float2(*(__half2*)&u.x);
    float2 f1 = __half22float2(*(__half2*)&u.y);
    float2 f2 = __half22float2(*(__half2*)&u.z);
    float2 f3 = __half22float2(*(__half2*)&u.w);
    float4 v0 = make_float4(f0.x, f0.y, f1.x, f1.y);
    float4 v1 = make_float4(f2.x, f2.y, f3.x, f3.y);
    ln_body(v0, v1, g, b, lane, out + row * 256 + lane * 8);
}

// ---------------------------------------------------------------------------
// fp16 tensor-core GEMM: CTA 128x128, warp 32x64, 3-stage cp.async,
// 2 CTAs/SM, one sync per chunk.
// MODE: 2=bias+gelu fp16 out; 3=bias fp16 out;
//       4=bias + fp32-res -> fp16 out; 5=bias + fp16-res -> fp32 out.
// ---------------------------------------------------------------------------
#define HSTAGE 32768
#define HSMEM  (3*HSTAGE)

template<int MODE>
__global__ __launch_bounds__(256, 2) void hgemm(
    const __half* __restrict__ A, const __half* __restrict__ B,
    const float* __restrict__ bias, const void* __restrict__ res,
    void* __restrict__ Cout, int N, int K)
{
    extern __shared__ char sm[];
    const uint32_t sbase = smem_u32(sm);
    const int tid  = threadIdx.x;
    const int lane = tid & 31;
    const int warp = tid >> 5;
    const int wr   = warp >> 1;
    const int wc   = warp & 1;
    const size_t gr0 = (size_t)blockIdx.y * 128;
    const int    gc0 = blockIdx.x * 128;
    const int CCH = K >> 6;

    const int lrow = tid >> 3;
    const int lkc  = tid & 7;

    auto load_stage = [&](int c) {
        uint32_t sA = sbase + (c % 3) * HSTAGE;
        uint32_t sB = sA + 16384;
        const __half* Ab = A + c*64 + lkc*8;
        const __half* Bb = B + c*64 + lkc*8;
        #pragma unroll
        for (int p = 0; p < 4; p++) {
            int row = lrow + p*32;
            uint32_t off = row*128 + (((uint32_t)(lkc ^ (row & 7))) << 4);
            CP_ASYNC16(sA + off, Ab + (gr0 + row) * (size_t)K);
            CP_ASYNC16(sB + off, Bb + (size_t)(gc0 + row) * K);
        }
    };

    load_stage(0); CP_COMMIT();
    load_stage(1); CP_COMMIT();

    float acc[2][8][4];
    #pragma unroll
    for (int mt = 0; mt < 2; mt++)
        #pragma unroll
        for (int nt = 0; nt < 8; nt++)
            #pragma unroll
            for (int q = 0; q < 4; q++) acc[mt][nt][q] = 0.0f;

    const int lr8  = (lane & 7) + ((lane >> 3) & 1) * 8;
    const int lkhi = lane >> 4;

    for (int c = 0; c < CCH; c++) {
        CP_WAIT1();
        __syncthreads();
        if (c + 2 < CCH) load_stage(c + 2);
        CP_COMMIT();

        uint32_t sA = sbase + (c % 3) * HSTAGE;
        uint32_t sB = sA + 16384;

        #pragma unroll
        for (int ks = 0; ks < 4; ks++) {
            int kc = 2*ks + lkhi;
            uint32_t a[2][4];
            #pragma unroll
            for (int mt = 0; mt < 2; mt++) {
                int row = wr*32 + mt*16 + lr8;
                LDSM_X4(a[mt][0], a[mt][1], a[mt][2], a[mt][3],
                        sA + row*128 + ((uint32_t)(kc ^ (row & 7)) << 4));
            }
            uint32_t b[4][4];
            #pragma unroll
            for (int nq = 0; nq < 4; nq++) {
                int row = wc*64 + nq*16 + lr8;
                LDSM_X4(b[nq][0], b[nq][1], b[nq][2], b[nq][3],
                        sB + row*128 + ((uint32_t)(kc ^ (row & 7)) << 4));
            }
            #pragma unroll
            for (int mt = 0; mt < 2; mt++)
                #pragma unroll
                for (int nt = 0; nt < 8; nt++)
                    MMA16816(acc[mt][nt], a[mt], b[nt>>1][nt&1], b[nt>>1][2+(nt&1)]);
        }
    }

    CP_WAIT0();
    __syncthreads();
    const int mrow = lane >> 2;
    const int ncol = (lane & 3) * 2;

    if (MODE == 2 || MODE == 3) {
        // ---- fp16 staging: bias(+gelu) in fragment space, 8-iter store ----
        __half* epi = (__half*)sm;
        float2 bias2[8];
        #pragma unroll
        for (int nt = 0; nt < 8; nt++)
            bias2[nt] = *(const float2*)(bias + gc0 + wc*64 + nt*8 + ncol);
        #pragma unroll
        for (int mt = 0; mt < 2; mt++)
            #pragma unroll
            for (int half = 0; half < 2; half++) {
                int r = wr*32 + mt*16 + half*8 + mrow;
                #pragma unroll
                for (int nt = 0; nt < 8; nt++) {
                    int cc = wc*64 + nt*8 + ncol;
                    float v0 = acc[mt][nt][half*2]   + bias2[nt].x;
                    float v1 = acc[mt][nt][half*2+1] + bias2[nt].y;
                    if (MODE == 2) { v0 = gelu_f(v0); v1 = gelu_f(v1); }
                    *(uint32_t*)&epi[r*136 + cc] = pack_h2(v0, v1);
                }
            }
        __syncthreads();
        #pragma unroll
        for (int it = 0; it < 8; it++) {
            int idx = it*256 + tid;
            int row = idx >> 4;
            int c8  = (idx & 15) * 8;
            uint4 v = *(uint4*)&epi[row*136 + c8];
            *(uint4*)((__half*)Cout + (gr0 + row) * (size_t)N + gc0 + c8) = v;
        }
    } else {
        // ---- fp32 staging with residual (MODE 4: fp32 res -> fp16 out;
        //                                  MODE 5: fp16 res -> fp32 out) ----
        float* epi = (float*)sm;
        #pragma unroll
        for (int mt = 0; mt < 2; mt++)
            #pragma unroll
            for (int half = 0; half < 2; half++) {
                int r = wr*32 + mt*16 + half*8 + mrow;
                #pragma unroll
                for (int nt = 0; nt < 8; nt++) {
                    int cc = wc*64 + nt*8 + ncol;
                    *(float2*)&epi[r*132 + cc] =
                        make_float2(acc[mt][nt][half*2], acc[mt][nt][half*2+1]);
                }
            }
        __syncthreads();
        #pragma unroll 4
        for (int it = 0; it < 16; it++) {
            int idx = it*256 + tid;
            int row = idx >> 5;
            int c4  = (idx & 31) * 4;
            int gcol = gc0 + c4;
            float4 v = *(float4*)&epi[row*132 + c4];
            float4 bb = *(const float4*)(bias + gcol);
            v.x += bb.x; v.y += bb.y; v.z += bb.z; v.w += bb.w;
            size_t grow = gr0 + row;
            if (MODE == 4) {
                float4 r = *(const float4*)((const float*)res + grow * (size_t)N + gcol);
                v.x += r.x; v.y += r.y; v.z += r.z; v.w += r.w;
                *(uint2*)((__half*)Cout + grow * (size_t)N + gcol) = pack_h4(v);
            } else {  // MODE 5
                uint2 ru = *(const uint2*)((const __half*)res + grow * (size_t)N + gcol);
                float2 f0 = __half22float2(*(__half2*)&ru.x);
                float2 f1 = __half22float2(*(__half2*)&ru.y);
                v.x += f0.x; v.y += f0.y; v.z += f1.x; v.w += f1.y;
                *(float4*)((float*)Cout + grow * (size_t)N + gcol) = v;
            }
        }
    }
}

// ---------------------------------------------------------------------------
// Fused shifted-window attention via mma.sync fp16 (R16: register cb).
// ---------------------------------------------------------------------------
__global__ __launch_bounds__(128) void attn_kernel(
    const __half* __restrict__ qkv, const __half* __restrict__ cb,
    __half* __restrict__ aoi)
{
    __shared__ __align__(16) __half qk_s[64*64];
    __shared__ __align__(16) __half v_s[32*64];

    const int head = blockIdx.x;
    const int w    = blockIdx.y;
    const int bimg = w >> 8;
    const int wimg = w & 255;
    const int wh   = wimg >> 4;
    const int ww   = wimg & 15;
    const int tid  = threadIdx.x;
    const int lane = tid & 31;
    const int wp   = tid >> 5;
    const uint32_t qkb = smem_u32(qk_s), vb = smem_u32(v_s);
    const float scale = 0.17677669529663689f;

    {
        const int dp = (tid & 15) * 2;
        const uint32_t ch = dp >> 3;
        const uint32_t wi = (dp & 7) * 2;
        #pragma unroll
        for (int it = 0; it < 8; it++) {
            int r = (tid >> 4) + 8*it;
            int i = r >> 3, j = r & 7;
            int oh = (wh*8 + i + 4) & 127;
            int ow = (ww*8 + j + 4) & 127;
            size_t tok = (size_t)bimg*16384 + oh*128 + ow;
            const __half* src = qkv + tok*768 + head*32 + dp;
            __half2 qh = *(const __half2*)(src);
            __half2 kh = *(const __half2*)(src + 256);
            __half2 vh = *(const __half2*)(src + 512);
            float2 qf = __half22float2(qh);
            uint32_t qp = pack_h2(qf.x * scale, qf.y * scale);
            uint32_t qa = r*128 + ((ch ^ (uint32_t)(r&7))<<4) + wi;
            uint32_t ka = r*128 + (((ch+4) ^ (uint32_t)(r&7))<<4) + wi;
            *(uint32_t*)((char*)qk_s + qa) = qp;
            *(uint32_t*)((char*)qk_s + ka) = *(uint32_t*)&kh;
            uint32_t va0 = dp*128     + ((uint32_t)((r>>3) ^ (dp&7))    <<4) + (r&7)*2;
            uint32_t va1 = (dp+1)*128 + ((uint32_t)((r>>3) ^ ((dp+1)&7))<<4) + (r&7)*2;
            *(__half*)((char*)v_s + va0) = __low2half(vh);
            *(__half*)((char*)v_s + va1) = __high2half(vh);
        }
    }

    const int r0 = wp*16 + (lane >> 2);
    const int r1 = r0 + 8;
    const int mcol = (lane & 3) * 2;
    __half2 cbr0[8], cbr1[8];
    {
        const __half* cbp = cb + ((size_t)wimg*8 + head)*4096;
        #pragma unroll
        for (int nt = 0; nt < 8; nt++) {
            cbr0[nt] = *(const __half2*)&cbp[r0*64 + nt*8 + mcol];
            cbr1[nt] = *(const __half2*)&cbp[r1*64 + nt*8 + mcol];
        }
    }
    __syncthreads();

    const int lr8  = (lane & 7) + ((lane >> 3) & 1) * 8;
    const int lkhi = lane >> 4;

    float acc[8][4];
    #pragma unroll
    for (int nt = 0; nt < 8; nt++)
        #pragma unroll
        for (int q = 0; q < 4; q++) acc[nt][q] = 0.0f;

    #pragma unroll
    for (int ks = 0; ks < 2; ks++) {
        int arow = wp*16 + lr8;
        int kcq  = 2*ks + lkhi;
        uint32_t a[4];
        LDSM_X4(a[0], a[1], a[2], a[3],
                qkb + arow*128 + ((uint32_t)(kcq ^ (arow & 7)) << 4));
        uint32_t b[4][4];
        #pragma unroll
        for (int nq = 0; nq < 4; nq++) {
            int brow = nq*16 + lr8;
            int kck  = 4 + 2*ks + lkhi;
            LDSM_X4(b[nq][0], b[nq][1], b[nq][2], b[nq][3],
                    qkb + brow*128 + ((uint32_t)(kck ^ (brow & 7)) << 4));
        }
        #pragma unroll
        for (int nt = 0; nt < 8; nt++)
            MMA16816(acc[nt], a, b[nt>>1][nt&1], b[nt>>1][2+(nt&1)]);
    }

    float mx0 = -1e30f, mx1 = -1e30f;
    #pragma unroll
    for (int nt = 0; nt < 8; nt++) {
        float2 f0 = __half22float2(cbr0[nt]);
        float2 f1 = __half22float2(cbr1[nt]);
        acc[nt][0] += f0.x; acc[nt][1] += f0.y;
        acc[nt][2] += f1.x; acc[nt][3] += f1.y;
        mx0 = fmaxf(mx0, fmaxf(acc[nt][0], acc[nt][1]));
        mx1 = fmaxf(mx1, fmaxf(acc[nt][2], acc[nt][3]));
    }
    mx0 = fmaxf(mx0, __shfl_xor_sync(0xffffffffu, mx0, 1));
    mx0 = fmaxf(mx0, __shfl_xor_sync(0xffffffffu, mx0, 2));
    mx1 = fmaxf(mx1, __shfl_xor_sync(0xffffffffu, mx1, 1));
    mx1 = fmaxf(mx1, __shfl_xor_sync(0xffffffffu, mx1, 2));
    float s0 = 0.0f, s1 = 0.0f;
    #pragma unroll
    for (int nt = 0; nt < 8; nt++) {
        acc[nt][0] = __expf(acc[nt][0] - mx0); s0 += acc[nt][0];
        acc[nt][1] = __expf(acc[nt][1] - mx0); s0 += acc[nt][1];
        acc[nt][2] = __expf(acc[nt][2] - mx1); s1 += acc[nt][2];
        acc[nt][3] = __expf(acc[nt][3] - mx1); s1 += acc[nt][3];
    }
    s0 += __shfl_xor_sync(0xffffffffu, s0, 1);
    s0 += __shfl_xor_sync(0xffffffffu, s0, 2);
    s1 += __shfl_xor_sync(0xffffffffu, s1, 1);
    s1 += __shfl_xor_sync(0xffffffffu, s1, 2);
    float inv0 = 1.0f / s0, inv1 = 1.0f / s1;

    float o[4][4];
    #pragma unroll
    for (int nt = 0; nt < 4; nt++)
        #pragma unroll
        for (int q = 0; q < 4; q++) o[nt][q] = 0.0f;

    #pragma unroll
    for (int kt = 0; kt < 4; kt++) {
        uint32_t a[4];
        a[0] = pack_h2(acc[2*kt][0]*inv0,   acc[2*kt][1]*inv0);
        a[1] = pack_h2(acc[2*kt][2]*inv1,   acc[2*kt][3]*inv1);
        a[2] = pack_h2(acc[2*kt+1][0]*inv0, acc[2*kt+1][1]*inv0);
        a[3] = pack_h2(acc[2*kt+1][2]*inv1, acc[2*kt+1][3]*inv1);
        uint32_t b[2][4];
        #pragma unroll
        for (int nq = 0; nq < 2; nq++) {
            int brow = nq*16 + lr8;
            int kc   = 2*kt + lkhi;
            LDSM_X4(b[nq][0], b[nq][1], b[nq][2], b[nq][3],
                    vb + brow*128 + ((uint32_t)(kc ^ (brow & 7)) << 4));
        }
        #pragma unroll
        for (int nt = 0; nt < 4; nt++)
            MMA16816(o[nt], a, b[nt>>1][nt&1], b[nt>>1][2+(nt&1)]);
    }

    #pragma unroll
    for (int s = 0; s < 2; s++) {
        int n = s ? r1 : r0;
        int i = n >> 3, j = n & 7;
        int oh = (wh*8 + i + 4) & 127;
        int ow = (ww*8 + j + 4) & 127;
        size_t tok = (size_t)bimg*16384 + oh*128 + ow;
        __half* base = aoi + tok*256 + head*32;
        #pragma unroll
        for (int nt = 0; nt < 4; nt++) {
            int c = nt*8 + (lane & 3)*2;
            *(uint32_t*)(base + c) = pack_h2(o[nt][s*2], o[nt][s*2+1]);
        }
    }
}

// ---------------------------------------------------------------------------
extern "C" void kernel_launch(void* const* d_in, const int* in_sizes, int n_in,
                              void* d_out, int out_size)
{
    const float* x     = (const float*)d_in[0];
    const float* mask  = (const float*)d_in[1];
    const float* n1g   = (const float*)d_in[2];
    const float* n1b   = (const float*)d_in[3];
    const float* qkvw  = (const float*)d_in[4];
    const float* qkvb  = (const float*)d_in[5];
    const float* relb  = (const float*)d_in[6];
    const float* projw = (const float*)d_in[7];
    const float* projb = (const float*)d_in[8];
    const float* n2g   = (const float*)d_in[9];
    const float* n2b   = (const float*)d_in[10];
    const float* fc1w  = (const float*)d_in[11];
    const float* fc1b  = (const float*)d_in[12];
    const float* fc2w  = (const float*)d_in[13];
    const float* fc2b  = (const float*)d_in[14];
    float* out = (float*)d_out;

    __half *xni, *qkv, *aoi, *x2h, *hidi, *qkvwi, *projwi, *fc1wi, *fc2wi, *cb;
    cudaGetSymbolAddress((void**)&xni,   g_xni);
    cudaGetSymbolAddress((void**)&qkv,   g_qkv);
    cudaGetSymbolAddress((void**)&aoi,   g_aoi);
    cudaGetSymbolAddress((void**)&x2h,   g_x2);
    cudaGetSymbolAddress((void**)&hidi,  g_hidi);
    cudaGetSymbolAddress((void**)&qkvwi, g_qkvwi);
    cudaGetSymbolAddress((void**)&projwi,g_projwi);
    cudaGetSymbolAddress((void**)&fc1wi, g_fc1wi);
    cudaGetSymbolAddress((void**)&fc2wi, g_fc2wi);
    cudaGetSymbolAddress((void**)&cb,    g_cb);

    cudaFuncSetAttribute(hgemm<2>, cudaFuncAttributeMaxDynamicSharedMemorySize, HSMEM);
    cudaFuncSetAttribute(hgemm<3>, cudaFuncAttributeMaxDynamicSharedMemorySize, HSMEM);
    cudaFuncSetAttribute(hgemm<4>, cudaFuncAttributeMaxDynamicSharedMemorySize, HSMEM);
    cudaFuncSetAttribute(hgemm<5>, cudaFuncAttributeMaxDynamicSharedMemorySize, HSMEM);

    wconv_all<<<768, 256>>>(qkvw, qkvwi, projw, projwi, fc1w, fc1wi, fc2w, fc2wi);
    cb_prep<<<16384, 256>>>(relb, mask, cb);

    // 1. LN1 -> fp16
    ln_kernel_f32<<<MT/8, 256>>>(x, n1g, n1b, xni);
    // 2. QKV: [131072,256] @ [768,256]^T -> fp16
    hgemm<3><<<dim3(6, MT/128), 256, HSMEM>>>(xni, qkvwi, qkvb, nullptr, qkv, 768, 256);
    // 3. windowed attention (tensor-core)
    attn_kernel<<<dim3(8, 2048), 128>>>(qkv, cb, aoi);
    // 4. proj + residual(x fp32) -> x2 fp16
    hgemm<4><<<dim3(2, MT/128), 256, HSMEM>>>(aoi, projwi, projb, x, x2h, 256, 256);
    // 5. LN2 (fp16 in) -> fp16
    ln_kernel_f16<<<MT/8, 256>>>(x2h, n2g, n2b, xni);
    // 6. FC1 + gelu -> fp16 hidden
    hgemm<2><<<dim3(8, MT/128), 256, HSMEM>>>(xni, fc1wi, fc1b, nullptr, hidi, 1024, 256);
    // 7. FC2 + residual(x2 fp16) -> out fp32
    hgemm<5><<<dim3(2, MT/128), 256, HSMEM>>>(hidi, fc2wi, fc2b, x2h, out, 256, 1024);
}